// round 1
// baseline (speedup 1.0000x reference)
#include <cuda_runtime.h>

#define Fdim 128
#define Hdim 128
#define TILE 64
#define NTHREADS 256
#define SA 72              // padded row stride (floats) for transposed A/H tiles
#define MAXN 50000

// Scratch (static device arrays: allocation-free per harness rules)
__device__ float g_mi[(size_t)MAXN * Hdim];   // aggregated messages per node
__device__ float g_dx[(size_t)MAXN * 3];      // aggregated coordinate deltas

// ---------------------------------------------------------------------------
__global__ void zero_kernel(int n_mi, int n_dx)
{
    int i = blockIdx.x * blockDim.x + threadIdx.x;
    if (i < n_mi) g_mi[i] = 0.0f;
    if (i < n_dx) g_dx[i] = 0.0f;
}

// ---------------------------------------------------------------------------
// Edge kernel: per 64-edge tile
//   e_in = [h_i(128) | h_j(128) | sqdist(1)]  (K = 257)
//   hidden = relu(e_in @ We1 + be1)           (64x257x128 GEMM)
//   m_ij   = hidden @ We2 + be2               (64x128x128 GEMM)
//   w_ij   = m_ij @ Wx + bx                   (block reduction)
//   atomic scatter: g_mi[dst] += m_ij ; g_dx[dst] += dist * w_ij
// ---------------------------------------------------------------------------
__global__ __launch_bounds__(NTHREADS, 2)
void edge_kernel(const float* __restrict__ node,
                 const float* __restrict__ coord,
                 const int*   __restrict__ ei,
                 const float* __restrict__ We1,
                 const float* __restrict__ be1,
                 const float* __restrict__ We2,
                 const float* __restrict__ be2,
                 const float* __restrict__ Wx,
                 const float* __restrict__ bxp,
                 int E)
{
    extern __shared__ float s[];
    float* sAH   = s;                      // 257*SA floats; rows 0..127 aliased as sH later
    float* sB    = s + 257 * SA;           // 16*128 weight panel
    float* sDist = sB + 16 * 128;          // 64*3
    float* sW    = sDist + TILE * 3;       // 64 edge weights (reduction target)
    int*   sDst  = (int*)(sW + TILE);      // 64 dst indices

    const int t  = threadIdx.x;
    const int e0 = blockIdx.x * TILE;

    // ---- stage e_in (transposed [k][e]) + per-edge metadata ----
    {
        int e  = t & 63;
        int c  = t >> 6;                   // quarter of K handled by this thread
        int eg = e0 + e;
        if (eg < E) {
            int si = ei[eg];               // src (j)
            int di = ei[E + eg];           // dst (i)
            const float* srow = (c < 2) ? (node + (size_t)di * Fdim + c * 64)
                                        : (node + (size_t)si * Fdim + (c - 2) * 64);
            int kb = c * 64;
            #pragma unroll
            for (int r = 0; r < 16; ++r) {
                float4 v = *(const float4*)(srow + r * 4);
                int k = kb + r * 4;
                sAH[(k + 0) * SA + e] = v.x;
                sAH[(k + 1) * SA + e] = v.y;
                sAH[(k + 2) * SA + e] = v.z;
                sAH[(k + 3) * SA + e] = v.w;
            }
            if (c == 0) {
                float ax = coord[(size_t)di * 3 + 0] - coord[(size_t)si * 3 + 0];
                float ay = coord[(size_t)di * 3 + 1] - coord[(size_t)si * 3 + 1];
                float az = coord[(size_t)di * 3 + 2] - coord[(size_t)si * 3 + 2];
                sDist[e * 3 + 0] = ax;
                sDist[e * 3 + 1] = ay;
                sDist[e * 3 + 2] = az;
                sAH[256 * SA + e] = ax * ax + ay * ay + az * az;
                sW[e]   = bxp[0];
                sDst[e] = di;
            }
        } else if (c == 0) {
            sW[e]   = 0.0f;
            sDst[e] = -1;
            sAH[256 * SA + e] = 0.0f;
        }
    }
    __syncthreads();

    const int m = t & 15;                  // edge group: edges 4m..4m+3
    const int g = t >> 4;                  // hidden group: h = 8g..8g+7

    // ---- MLP layer 1: acc = e_in @ We1 + be1 ----
    float acc[4][8];
    {
        float4 b0 = *(const float4*)(be1 + g * 8);
        float4 b1 = *(const float4*)(be1 + g * 8 + 4);
        #pragma unroll
        for (int i = 0; i < 4; ++i) {
            acc[i][0] = b0.x; acc[i][1] = b0.y; acc[i][2] = b0.z; acc[i][3] = b0.w;
            acc[i][4] = b1.x; acc[i][5] = b1.y; acc[i][6] = b1.z; acc[i][7] = b1.w;
        }
    }

    for (int kk = 0; kk < 256; kk += 16) {
        {   // stage 16x128 panel of We1
            int idx = t * 8;
            int r   = idx >> 7;
            int cc  = idx & 127;
            const float* src = We1 + (size_t)(kk + r) * Hdim + cc;
            *(float4*)(sB + idx)     = *(const float4*)src;
            *(float4*)(sB + idx + 4) = *(const float4*)(src + 4);
        }
        __syncthreads();
        #pragma unroll
        for (int k = 0; k < 16; ++k) {
            float4 a  = *(const float4*)(sAH + (kk + k) * SA + m * 4);
            float4 w0 = *(const float4*)(sB + k * 128 + g * 8);
            float4 w1 = *(const float4*)(sB + k * 128 + g * 8 + 4);
            float av[4] = {a.x, a.y, a.z, a.w};
            float wv[8] = {w0.x, w0.y, w0.z, w0.w, w1.x, w1.y, w1.z, w1.w};
            #pragma unroll
            for (int i = 0; i < 4; ++i)
                #pragma unroll
                for (int j = 0; j < 8; ++j)
                    acc[i][j] = fmaf(av[i], wv[j], acc[i][j]);
        }
        __syncthreads();
    }
    {   // K tail: k = 256 (sqdist row); weights straight from L2
        float4 a  = *(const float4*)(sAH + 256 * SA + m * 4);
        float4 w0 = *(const float4*)(We1 + 256 * Hdim + g * 8);
        float4 w1 = *(const float4*)(We1 + 256 * Hdim + g * 8 + 4);
        float av[4] = {a.x, a.y, a.z, a.w};
        float wv[8] = {w0.x, w0.y, w0.z, w0.w, w1.x, w1.y, w1.z, w1.w};
        #pragma unroll
        for (int i = 0; i < 4; ++i)
            #pragma unroll
            for (int j = 0; j < 8; ++j)
                acc[i][j] = fmaf(av[i], wv[j], acc[i][j]);
    }
    __syncthreads();

    // ---- relu + transpose hidden into sH (aliases sAH rows 0..127) ----
    #pragma unroll
    for (int j = 0; j < 8; ++j) {
        int h = g * 8 + j;
        float4 v;
        v.x = fmaxf(acc[0][j], 0.0f);
        v.y = fmaxf(acc[1][j], 0.0f);
        v.z = fmaxf(acc[2][j], 0.0f);
        v.w = fmaxf(acc[3][j], 0.0f);
        *(float4*)(sAH + h * SA + m * 4) = v;
    }
    __syncthreads();

    // ---- MLP layer 2: acc2 = hidden @ We2 + be2 ----
    float acc2[4][8];
    {
        float4 b0 = *(const float4*)(be2 + g * 8);
        float4 b1 = *(const float4*)(be2 + g * 8 + 4);
        #pragma unroll
        for (int i = 0; i < 4; ++i) {
            acc2[i][0] = b0.x; acc2[i][1] = b0.y; acc2[i][2] = b0.z; acc2[i][3] = b0.w;
            acc2[i][4] = b1.x; acc2[i][5] = b1.y; acc2[i][6] = b1.z; acc2[i][7] = b1.w;
        }
    }

    for (int kk = 0; kk < 128; kk += 16) {
        {
            int idx = t * 8;
            int r   = idx >> 7;
            int cc  = idx & 127;
            const float* src = We2 + (size_t)(kk + r) * Hdim + cc;
            *(float4*)(sB + idx)     = *(const float4*)src;
            *(float4*)(sB + idx + 4) = *(const float4*)(src + 4);
        }
        __syncthreads();
        #pragma unroll
        for (int k = 0; k < 16; ++k) {
            float4 a  = *(const float4*)(sAH + (kk + k) * SA + m * 4);
            float4 w0 = *(const float4*)(sB + k * 128 + g * 8);
            float4 w1 = *(const float4*)(sB + k * 128 + g * 8 + 4);
            float av[4] = {a.x, a.y, a.z, a.w};
            float wv[8] = {w0.x, w0.y, w0.z, w0.w, w1.x, w1.y, w1.z, w1.w};
            #pragma unroll
            for (int i = 0; i < 4; ++i)
                #pragma unroll
                for (int j = 0; j < 8; ++j)
                    acc2[i][j] = fmaf(av[i], wv[j], acc2[i][j]);
        }
        __syncthreads();
    }

    // ---- w_ij = m_ij @ Wx + bx : partial dot + shared-atomic reduce ----
    {
        float4 x0 = *(const float4*)(Wx + g * 8);
        float4 x1 = *(const float4*)(Wx + g * 8 + 4);
        float wx[8] = {x0.x, x0.y, x0.z, x0.w, x1.x, x1.y, x1.z, x1.w};
        #pragma unroll
        for (int i = 0; i < 4; ++i) {
            float p = 0.0f;
            #pragma unroll
            for (int j = 0; j < 8; ++j) p = fmaf(acc2[i][j], wx[j], p);
            atomicAdd(&sW[m * 4 + i], p);
        }
    }
    __syncthreads();

    // ---- scatter delta_x contributions ----
    if (t < TILE * 3) {
        int e = t / 3;
        int d = t - e * 3;
        int di = sDst[e];
        if (di >= 0)
            atomicAdd(&g_dx[(size_t)di * 3 + d], sDist[e * 3 + d] * sW[e]);
    }

    // ---- scatter m_ij into g_mi ----
    #pragma unroll
    for (int i = 0; i < 4; ++i) {
        int di = sDst[m * 4 + i];
        if (di >= 0) {
            float* p = g_mi + (size_t)di * Hdim + g * 8;
            #pragma unroll
            for (int j = 0; j < 8; ++j) atomicAdd(p + j, acc2[i][j]);
        }
    }
}

// ---------------------------------------------------------------------------
// Node kernel: h_new = relu([node | m_i] @ Wh1 + bh1) @ Wh2 + bh2
// ---------------------------------------------------------------------------
__global__ __launch_bounds__(NTHREADS, 2)
void node_kernel(const float* __restrict__ node,
                 const float* __restrict__ Wh1,
                 const float* __restrict__ bh1,
                 const float* __restrict__ Wh2,
                 const float* __restrict__ bh2,
                 float* __restrict__ outH,
                 int N)
{
    extern __shared__ float s[];
    float* sAH = s;                        // 256*SA (rows 0..127 aliased as sH later)
    float* sB  = s + 256 * SA;             // 16*128

    const int t  = threadIdx.x;
    const int r0 = blockIdx.x * TILE;

    {   // stage h_in transposed [k][n]
        int n   = t & 63;
        int c   = t >> 6;
        int row = r0 + n;
        if (row < N) {
            const float* srow = (c < 2) ? (node + (size_t)row * Fdim + c * 64)
                                        : (g_mi + (size_t)row * Hdim + (c - 2) * 64);
            int kb = c * 64;
            #pragma unroll
            for (int r = 0; r < 16; ++r) {
                float4 v = *(const float4*)(srow + r * 4);
                int k = kb + r * 4;
                sAH[(k + 0) * SA + n] = v.x;
                sAH[(k + 1) * SA + n] = v.y;
                sAH[(k + 2) * SA + n] = v.z;
                sAH[(k + 3) * SA + n] = v.w;
            }
        }
    }
    __syncthreads();

    const int m = t & 15;
    const int g = t >> 4;

    float acc[4][8];
    {
        float4 b0 = *(const float4*)(bh1 + g * 8);
        float4 b1 = *(const float4*)(bh1 + g * 8 + 4);
        #pragma unroll
        for (int i = 0; i < 4; ++i) {
            acc[i][0] = b0.x; acc[i][1] = b0.y; acc[i][2] = b0.z; acc[i][3] = b0.w;
            acc[i][4] = b1.x; acc[i][5] = b1.y; acc[i][6] = b1.z; acc[i][7] = b1.w;
        }
    }

    for (int kk = 0; kk < 256; kk += 16) {
        {
            int idx = t * 8;
            int r   = idx >> 7;
            int cc  = idx & 127;
            const float* src = Wh1 + (size_t)(kk + r) * Hdim + cc;
            *(float4*)(sB + idx)     = *(const float4*)src;
            *(float4*)(sB + idx + 4) = *(const float4*)(src + 4);
        }
        __syncthreads();
        #pragma unroll
        for (int k = 0; k < 16; ++k) {
            float4 a  = *(const float4*)(sAH + (kk + k) * SA + m * 4);
            float4 w0 = *(const float4*)(sB + k * 128 + g * 8);
            float4 w1 = *(const float4*)(sB + k * 128 + g * 8 + 4);
            float av[4] = {a.x, a.y, a.z, a.w};
            float wv[8] = {w0.x, w0.y, w0.z, w0.w, w1.x, w1.y, w1.z, w1.w};
            #pragma unroll
            for (int i = 0; i < 4; ++i)
                #pragma unroll
                for (int j = 0; j < 8; ++j)
                    acc[i][j] = fmaf(av[i], wv[j], acc[i][j]);
        }
        __syncthreads();
    }

    #pragma unroll
    for (int j = 0; j < 8; ++j) {
        int h = g * 8 + j;
        float4 v;
        v.x = fmaxf(acc[0][j], 0.0f);
        v.y = fmaxf(acc[1][j], 0.0f);
        v.z = fmaxf(acc[2][j], 0.0f);
        v.w = fmaxf(acc[3][j], 0.0f);
        *(float4*)(sAH + h * SA + m * 4) = v;
    }
    __syncthreads();

    float acc2[4][8];
    {
        float4 b0 = *(const float4*)(bh2 + g * 8);
        float4 b1 = *(const float4*)(bh2 + g * 8 + 4);
        #pragma unroll
        for (int i = 0; i < 4; ++i) {
            acc2[i][0] = b0.x; acc2[i][1] = b0.y; acc2[i][2] = b0.z; acc2[i][3] = b0.w;
            acc2[i][4] = b1.x; acc2[i][5] = b1.y; acc2[i][6] = b1.z; acc2[i][7] = b1.w;
        }
    }

    for (int kk = 0; kk < 128; kk += 16) {
        {
            int idx = t * 8;
            int r   = idx >> 7;
            int cc  = idx & 127;
            const float* src = Wh2 + (size_t)(kk + r) * Fdim + cc;
            *(float4*)(sB + idx)     = *(const float4*)src;
            *(float4*)(sB + idx + 4) = *(const float4*)(src + 4);
        }
        __syncthreads();
        #pragma unroll
        for (int k = 0; k < 16; ++k) {
            float4 a  = *(const float4*)(sAH + (kk + k) * SA + m * 4);
            float4 w0 = *(const float4*)(sB + k * 128 + g * 8);
            float4 w1 = *(const float4*)(sB + k * 128 + g * 8 + 4);
            float av[4] = {a.x, a.y, a.z, a.w};
            float wv[8] = {w0.x, w0.y, w0.z, w0.w, w1.x, w1.y, w1.z, w1.w};
            #pragma unroll
            for (int i = 0; i < 4; ++i)
                #pragma unroll
                for (int j = 0; j < 8; ++j)
                    acc2[i][j] = fmaf(av[i], wv[j], acc2[i][j]);
        }
        __syncthreads();
    }

    #pragma unroll
    for (int i = 0; i < 4; ++i) {
        int row = r0 + m * 4 + i;
        if (row < N) {
            float4 v0, v1;
            v0.x = acc2[i][0]; v0.y = acc2[i][1]; v0.z = acc2[i][2]; v0.w = acc2[i][3];
            v1.x = acc2[i][4]; v1.y = acc2[i][5]; v1.z = acc2[i][6]; v1.w = acc2[i][7];
            *(float4*)(outH + (size_t)row * Fdim + g * 8)     = v0;
            *(float4*)(outH + (size_t)row * Fdim + g * 8 + 4) = v1;
        }
    }
}

// ---------------------------------------------------------------------------
__global__ void x_kernel(const float* __restrict__ coord,
                         float* __restrict__ outX,
                         int n3, float C)
{
    int i = blockIdx.x * blockDim.x + threadIdx.x;
    if (i < n3) outX[i] = coord[i] + g_dx[i] * C;
}

// ---------------------------------------------------------------------------
extern "C" void kernel_launch(void* const* d_in, const int* in_sizes, int n_in,
                              void* d_out, int out_size)
{
    const float* node  = (const float*)d_in[0];
    const float* coord = (const float*)d_in[1];
    const int*   ei    = (const int*)d_in[2];
    const float* We1   = (const float*)d_in[3];
    const float* be1   = (const float*)d_in[4];
    const float* We2   = (const float*)d_in[5];
    const float* be2   = (const float*)d_in[6];
    const float* Wx    = (const float*)d_in[7];
    const float* bx    = (const float*)d_in[8];
    const float* Wh1   = (const float*)d_in[9];
    const float* bh1   = (const float*)d_in[10];
    const float* Wh2   = (const float*)d_in[11];
    const float* bh2   = (const float*)d_in[12];

    const int N = in_sizes[0] / Fdim;
    const int E = in_sizes[2] / 2;

    float* outH = (float*)d_out;
    float* outX = outH + (size_t)N * Fdim;

    const int edge_smem = (257 * SA + 16 * 128 + TILE * 3 + TILE + TILE) * 4;
    const int node_smem = (256 * SA + 16 * 128) * 4;
    cudaFuncSetAttribute(edge_kernel, cudaFuncAttributeMaxDynamicSharedMemorySize, edge_smem);
    cudaFuncSetAttribute(node_kernel, cudaFuncAttributeMaxDynamicSharedMemorySize, node_smem);

    // 1) zero scratch accumulators
    {
        int n_mi = N * Hdim;
        int n_dx = N * 3;
        int tot  = n_mi;                 // n_mi > n_dx always
        zero_kernel<<<(tot + 255) / 256, 256>>>(n_mi, n_dx);
    }

    // 2) edge pass (fused gather + 2-layer MLP + scalar head + atomic scatter)
    {
        int grid = (E + TILE - 1) / TILE;
        edge_kernel<<<grid, NTHREADS, edge_smem>>>(node, coord, ei,
                                                   We1, be1, We2, be2, Wx, bx, E);
    }

    // 3) node pass (fused concat + 2-layer MLP)
    {
        int grid = (N + TILE - 1) / TILE;
        node_kernel<<<grid, NTHREADS, node_smem>>>(node, Wh1, bh1, Wh2, bh2, outH, N);
    }

    // 4) coordinate update
    {
        int n3 = N * 3;
        float C = 1.0f / (float)(N - 1);
        x_kernel<<<(n3 + 255) / 256, 256>>>(coord, outX, n3, C);
    }
}

// round 3
// speedup vs baseline: 1.4063x; 1.4063x over previous
#include <cuda_runtime.h>
#include <cuda_bf16.h>
#include <cstdint>

#define Fdim 128
#define ET   128              // edges per tile (MMA M)
#define MAXN 50000
#define TILE 64               // node-kernel row tile
#define NTHREADS 256
#define SA 72                 // node-kernel fp32 padded stride
#define SAB 72                // edge-kernel bf16 padded stride (144 B rows)

// ---------------- scratch (static device arrays; allocation-free) ----------
__device__ float g_mi[(size_t)MAXN * 128];
__device__ float g_dx4[(size_t)MAXN * 4];
// pre-split padded weight images: [chunk][ hi(128*72) | lo(128*72) ] bf16, [n][k]
__device__ __nv_bfloat16 gB1[4][2 * 128 * SAB];
__device__ __nv_bfloat16 gB2[2][2 * 128 * SAB];

// ---------------- PTX helpers ----------------------------------------------
__device__ __forceinline__ uint32_t smem_u32(const void* p) {
    uint32_t a;
    asm("{ .reg .u64 t; cvta.to.shared.u64 t, %1; cvt.u32.u64 %0, t; }" : "=r"(a) : "l"(p));
    return a;
}

#define LDSM4(r0, r1, r2, r3, addr) \
    asm volatile("ldmatrix.sync.aligned.m8n8.x4.shared.b16 {%0,%1,%2,%3}, [%4];" \
                 : "=r"(r0), "=r"(r1), "=r"(r2), "=r"(r3) : "r"(addr))

#define MMA16816(cp, a0, a1, a2, a3, b0, b1) \
    asm volatile("mma.sync.aligned.m16n8k16.row.col.f32.bf16.bf16.f32 " \
                 "{%0,%1,%2,%3},{%4,%5,%6,%7},{%8,%9},{%0,%1,%2,%3};" \
                 : "+f"((cp)[0]), "+f"((cp)[1]), "+f"((cp)[2]), "+f"((cp)[3]) \
                 : "r"(a0), "r"(a1), "r"(a2), "r"(a3), "r"(b0), "r"(b1))

__device__ __forceinline__ void red2(float* p, float x, float y) {
    asm volatile("red.global.add.v2.f32 [%0], {%1,%2};" :: "l"(p), "f"(x), "f"(y) : "memory");
}
__device__ __forceinline__ void red4(float* p, float4 v) {
    asm volatile("red.global.add.v4.f32 [%0], {%1,%2,%3,%4};"
                 :: "l"(p), "f"(v.x), "f"(v.y), "f"(v.z), "f"(v.w) : "memory");
}

// pack two floats -> bf16x2 (lower = a, upper = b)
__device__ __forceinline__ uint32_t packbf2(float a, float b) {
    uint32_t r;
    asm("cvt.rn.bf16x2.f32 %0, %1, %2;" : "=r"(r) : "f"(b), "f"(a));
    return r;
}

// split 8 floats into hi/lo bf16x2 quads
__device__ __forceinline__ void split8(const float* v, uint4& H, uint4& L) {
    uint32_t h[4], l[4];
    #pragma unroll
    for (int i = 0; i < 4; ++i) {
        float a = v[2 * i], b = v[2 * i + 1];
        uint32_t hp = packbf2(a, b);
        float ah = __uint_as_float(hp << 16);
        float bh = __uint_as_float(hp & 0xFFFF0000u);
        h[i] = hp;
        l[i] = packbf2(a - ah, b - bh);
    }
    H = make_uint4(h[0], h[1], h[2], h[3]);
    L = make_uint4(l[0], l[1], l[2], l[3]);
}

// ---------------- prep: split weights into padded [n][k] images -------------
__global__ void prep_kernel(const float* __restrict__ We1, const float* __restrict__ We2)
{
    int id = blockIdx.x * blockDim.x + threadIdx.x;
    if (id < 32768) {                       // B1: 4 chunks x 128 n x 64 k
        int c   = id >> 13;
        int rem = id & 8191;
        int n   = rem >> 6;
        int kc  = rem & 63;
        float v = We1[(size_t)(c * 64 + kc) * 128 + n];
        __nv_bfloat16 hi = __float2bfloat16(v);
        float lo = v - __bfloat162float(hi);
        gB1[c][n * SAB + kc]              = hi;
        gB1[c][128 * SAB + n * SAB + kc]  = __float2bfloat16(lo);
    } else if (id < 49152) {                // B2: 2 chunks
        int id2 = id - 32768;
        int c   = id2 >> 13;
        int rem = id2 & 8191;
        int n   = rem >> 6;
        int kc  = rem & 63;
        float v = We2[(size_t)(c * 64 + kc) * 128 + n];
        __nv_bfloat16 hi = __float2bfloat16(v);
        float lo = v - __bfloat162float(hi);
        gB2[c][n * SAB + kc]              = hi;
        gB2[c][128 * SAB + n * SAB + kc]  = __float2bfloat16(lo);
    }
}

// ---------------- zero scratch ----------------------------------------------
__global__ void zero_kernel(int n_mi, int n_dx)
{
    int i = blockIdx.x * blockDim.x + threadIdx.x;
    if (i < n_mi) g_mi[i] = 0.0f;
    if (i < n_dx) g_dx4[i] = 0.0f;
}

// ---------------- edge kernel: mma.sync split-bf16 --------------------------
// SMEM bytes: A_HI 18432 | A_LO 18432 | B_HI 18432 | B_LO 18432 | misc
#define SO_AH   0
#define SO_AL   18432
#define SO_BH   36864
#define SO_BL   55296
#define SO_DS   73728      /* float4[128] */
#define SO_W    75776      /* float[128] */
#define SO_DST  76288      /* int[128] */
#define SO_WX   76800
#define SO_BE1  77312
#define SO_BE2  77824
#define SO_W256 78336
#define EDGE_SMEM 78848

__global__ __launch_bounds__(256, 1)
void edge_kernel(const float* __restrict__ node,
                 const float* __restrict__ coord,
                 const int*   __restrict__ ei,
                 const float* __restrict__ We1,
                 const float* __restrict__ be1,
                 const float* __restrict__ be2,
                 const float* __restrict__ Wx,
                 const float* __restrict__ bxp,
                 int E)
{
    extern __shared__ char sm[];
    const uint32_t sbase = smem_u32(sm);

    float4* sDS  = (float4*)(sm + SO_DS);
    float*  sW   = (float*)(sm + SO_W);
    int*    sDst = (int*)(sm + SO_DST);
    float*  sWx  = (float*)(sm + SO_WX);
    float*  sBe1 = (float*)(sm + SO_BE1);
    float*  sBe2 = (float*)(sm + SO_BE2);
    float*  sW256= (float*)(sm + SO_W256);

    const int t    = threadIdx.x;
    const int wid  = t >> 5;
    const int lane = t & 31;
    const int e0   = blockIdx.x * ET;
    const float bx = bxp[0];

    // ---- per-edge metadata ----
    if (t < ET) {
        int eg = e0 + t;
        float dx = 0.f, dy = 0.f, dz = 0.f;
        int di = -1;
        if (eg < E) {
            int si = ei[eg];
            di     = ei[E + eg];
            dx = coord[(size_t)di * 3 + 0] - coord[(size_t)si * 3 + 0];
            dy = coord[(size_t)di * 3 + 1] - coord[(size_t)si * 3 + 1];
            dz = coord[(size_t)di * 3 + 2] - coord[(size_t)si * 3 + 2];
        }
        sDS[t]  = make_float4(dx, dy, dz, dx * dx + dy * dy + dz * dz);
        sDst[t] = di;
        sWx[t]  = Wx[t];
        sBe1[t] = be1[t];
        sBe2[t] = be2[t];
        sW256[t]= We1[(size_t)256 * 128 + t];
    }

    // gather role: thread covers row = t/2, cols half*32..+31
    const int grow = t >> 1;
    const int ghalf = t & 1;
    int gsi = 0, gdi = 0;
    bool gvalid = (e0 + grow) < E;
    if (gvalid) { gsi = ei[e0 + grow]; gdi = ei[E + e0 + grow]; }

    // ldmatrix lane addressing
    const int seg = lane >> 3, ln = lane & 7;
    const uint32_t aoff = (uint32_t)((wid * 16 + ln + ((seg & 1) << 3)) * 144 + (((seg >> 1) & 1) << 4));
    const uint32_t boff0 = (uint32_t)((ln + ((seg >> 1) << 3)) * 144 + ((seg & 1) << 4));

    float c1[64];
    #pragma unroll
    for (int i = 0; i < 64; ++i) c1[i] = 0.0f;

    // ================= GEMM1: e_in[:,0:256] @ We1, 4 k-chunks of 64 =========
    #pragma unroll 1
    for (int c = 0; c < 4; ++c) {
        __syncthreads();
        {   // stage A chunk (gather + split)
            const float* rp = node + (size_t)(c < 2 ? gdi : gsi) * 128 + (c & 1) * 64 + ghalf * 32;
            uint32_t ab = (uint32_t)(grow * 144 + ghalf * 64);
            #pragma unroll
            for (int u = 0; u < 4; ++u) {
                float v[8];
                if (gvalid) {
                    float4 v0 = *(const float4*)(rp + u * 8);
                    float4 v1 = *(const float4*)(rp + u * 8 + 4);
                    v[0]=v0.x; v[1]=v0.y; v[2]=v0.z; v[3]=v0.w;
                    v[4]=v1.x; v[5]=v1.y; v[6]=v1.z; v[7]=v1.w;
                } else {
                    #pragma unroll
                    for (int q = 0; q < 8; ++q) v[q] = 0.0f;
                }
                uint4 H, L;
                split8(v, H, L);
                *(uint4*)(sm + SO_AH + ab + u * 16) = H;
                *(uint4*)(sm + SO_AL + ab + u * 16) = L;
            }
        }
        {   // copy B1 chunk (hi+lo contiguous: 36864 B = 2304 uint4)
            const uint4* src = (const uint4*)gB1[c];
            uint4* dst = (uint4*)(sm + SO_BH);
            #pragma unroll
            for (int it = 0; it < 9; ++it) dst[t + it * 256] = src[t + it * 256];
        }
        __syncthreads();

        #pragma unroll
        for (int ks = 0; ks < 4; ++ks) {
            uint32_t ah0,ah1,ah2,ah3, al0,al1,al2,al3;
            LDSM4(ah0,ah1,ah2,ah3, sbase + SO_AH + aoff + ks * 32);
            LDSM4(al0,al1,al2,al3, sbase + SO_AL + aoff + ks * 32);
            #pragma unroll
            for (int jb = 0; jb < 8; ++jb) {
                uint32_t bo = boff0 + (uint32_t)(jb * 16 * 144 + ks * 32);
                uint32_t bh0,bh1,bh2,bh3, bl0,bl1,bl2,bl3;
                LDSM4(bh0,bh1,bh2,bh3, sbase + SO_BH + bo);
                LDSM4(bl0,bl1,bl2,bl3, sbase + SO_BL + bo);
                float* cp0 = c1 + 8 * jb;
                float* cp1 = c1 + 8 * jb + 4;
                MMA16816(cp0, ah0,ah1,ah2,ah3, bh0,bh1);
                MMA16816(cp0, ah0,ah1,ah2,ah3, bl0,bl1);
                MMA16816(cp0, al0,al1,al2,al3, bh0,bh1);
                MMA16816(cp1, ah0,ah1,ah2,ah3, bh2,bh3);
                MMA16816(cp1, ah0,ah1,ah2,ah3, bl2,bl3);
                MMA16816(cp1, al0,al1,al2,al3, bh2,bh3);
            }
        }
    }

    // ============ epilogue1: relu(c1 + be1 + sqdist * We1[256,:]) ===========
    const int r0 = wid * 16 + (lane >> 2);
    const int q  = lane & 3;
    const float sq0 = sDS[r0].w;
    const float sq1 = sDS[r0 + 8].w;
    #pragma unroll
    for (int f = 0; f < 16; ++f) {
        int col = 8 * f + 2 * q;
        float2 b = *(float2*)(sBe1 + col);
        float2 w = *(float2*)(sW256 + col);
        c1[4*f+0] = fmaxf(c1[4*f+0] + b.x + sq0 * w.x, 0.0f);
        c1[4*f+1] = fmaxf(c1[4*f+1] + b.y + sq0 * w.y, 0.0f);
        c1[4*f+2] = fmaxf(c1[4*f+2] + b.x + sq1 * w.x, 0.0f);
        c1[4*f+3] = fmaxf(c1[4*f+3] + b.y + sq1 * w.y, 0.0f);
    }

    // ================= GEMM2: hidden @ We2 (A from registers) ===============
    float c2[64];
    #pragma unroll
    for (int i = 0; i < 64; ++i) c2[i] = 0.0f;

    #pragma unroll 1
    for (int r = 0; r < 2; ++r) {
        __syncthreads();
        {
            const uint4* src = (const uint4*)gB2[r];
            uint4* dst = (uint4*)(sm + SO_BH);
            #pragma unroll
            for (int it = 0; it < 9; ++it) dst[t + it * 256] = src[t + it * 256];
        }
        __syncthreads();

        #pragma unroll
        for (int ks = 0; ks < 4; ++ks) {
            const int f0 = r * 8 + ks * 2;
            uint32_t ah[4], al[4];
            #pragma unroll
            for (int i = 0; i < 4; ++i) {
                float va = c1[4 * f0 + 2 * i];
                float vb = c1[4 * f0 + 2 * i + 1];
                uint32_t hp = packbf2(va, vb);
                ah[i] = hp;
                float ea = __uint_as_float(hp << 16);
                float eb = __uint_as_float(hp & 0xFFFF0000u);
                al[i] = packbf2(va - ea, vb - eb);
            }
            #pragma unroll
            for (int jb = 0; jb < 8; ++jb) {
                uint32_t bo = boff0 + (uint32_t)(jb * 16 * 144 + ks * 32);
                uint32_t bh0,bh1,bh2,bh3, bl0,bl1,bl2,bl3;
                LDSM4(bh0,bh1,bh2,bh3, sbase + SO_BH + bo);
                LDSM4(bl0,bl1,bl2,bl3, sbase + SO_BL + bo);
                float* cp0 = c2 + 8 * jb;
                float* cp1 = c2 + 8 * jb + 4;
                MMA16816(cp0, ah[0],ah[1],ah[2],ah[3], bh0,bh1);
                MMA16816(cp0, ah[0],ah[1],ah[2],ah[3], bl0,bl1);
                MMA16816(cp0, al[0],al[1],al[2],al[3], bh0,bh1);
                MMA16816(cp1, ah[0],ah[1],ah[2],ah[3], bh2,bh3);
                MMA16816(cp1, ah[0],ah[1],ah[2],ah[3], bl2,bl3);
                MMA16816(cp1, al[0],al[1],al[2],al[3], bh2,bh3);
            }
        }
    }

    // ============ epilogue2: bias, scalar head, register-direct scatter =====
    const int dst0 = sDst[r0];
    const int dst1 = sDst[r0 + 8];
    float w0 = 0.0f, w1 = 0.0f;
    #pragma unroll
    for (int f = 0; f < 16; ++f) {
        int col = 8 * f + 2 * q;
        float2 b  = *(float2*)(sBe2 + col);
        float2 wx = *(float2*)(sWx + col);
        float v0 = c2[4*f+0] + b.x;
        float v1 = c2[4*f+1] + b.y;
        float v2 = c2[4*f+2] + b.x;
        float v3 = c2[4*f+3] + b.y;
        w0 = fmaf(v0, wx.x, fmaf(v1, wx.y, w0));
        w1 = fmaf(v2, wx.x, fmaf(v3, wx.y, w1));
        if (dst0 >= 0) red2(g_mi + (size_t)dst0 * 128 + col, v0, v1);
        if (dst1 >= 0) red2(g_mi + (size_t)dst1 * 128 + col, v2, v3);
    }
    // quad reduction for edge weights
    w0 += __shfl_xor_sync(0xffffffffu, w0, 1);
    w0 += __shfl_xor_sync(0xffffffffu, w0, 2);
    w1 += __shfl_xor_sync(0xffffffffu, w1, 1);
    w1 += __shfl_xor_sync(0xffffffffu, w1, 2);
    if (q == 0) {
        sW[r0]     = w0 + bx;
        sW[r0 + 8] = w1 + bx;
    }
    __syncthreads();

    if (t < ET) {
        int di = sDst[t];
        if (di >= 0) {
            float w = sW[t];
            float4 ds = sDS[t];
            red4(g_dx4 + (size_t)di * 4, make_float4(ds.x * w, ds.y * w, ds.z * w, 0.0f));
        }
    }
}

// ---------------- node kernel (round-1 FFMA, proven) ------------------------
__global__ __launch_bounds__(NTHREADS, 2)
void node_kernel(const float* __restrict__ node,
                 const float* __restrict__ Wh1,
                 const float* __restrict__ bh1,
                 const float* __restrict__ Wh2,
                 const float* __restrict__ bh2,
                 float* __restrict__ outH,
                 int N)
{
    extern __shared__ float s[];
    float* sAH = s;
    float* sB  = s + 256 * SA;

    const int t  = threadIdx.x;
    const int r0 = blockIdx.x * TILE;

    {
        int n   = t & 63;
        int c   = t >> 6;
        int row = r0 + n;
        if (row < N) {
            const float* srow = (c < 2) ? (node + (size_t)row * Fdim + c * 64)
                                        : (g_mi + (size_t)row * 128 + (c - 2) * 64);
            int kb = c * 64;
            #pragma unroll
            for (int r = 0; r < 16; ++r) {
                float4 v = *(const float4*)(srow + r * 4);
                int k = kb + r * 4;
                sAH[(k + 0) * SA + n] = v.x;
                sAH[(k + 1) * SA + n] = v.y;
                sAH[(k + 2) * SA + n] = v.z;
                sAH[(k + 3) * SA + n] = v.w;
            }
        }
    }
    __syncthreads();

    const int m = t & 15;
    const int g = t >> 4;

    float acc[4][8];
    {
        float4 b0 = *(const float4*)(bh1 + g * 8);
        float4 b1 = *(const float4*)(bh1 + g * 8 + 4);
        #pragma unroll
        for (int i = 0; i < 4; ++i) {
            acc[i][0] = b0.x; acc[i][1] = b0.y; acc[i][2] = b0.z; acc[i][3] = b0.w;
            acc[i][4] = b1.x; acc[i][5] = b1.y; acc[i][6] = b1.z; acc[i][7] = b1.w;
        }
    }

    for (int kk = 0; kk < 256; kk += 16) {
        {
            int idx = t * 8;
            int r   = idx >> 7;
            int cc  = idx & 127;
            const float* src = Wh1 + (size_t)(kk + r) * 128 + cc;
            *(float4*)(sB + idx)     = *(const float4*)src;
            *(float4*)(sB + idx + 4) = *(const float4*)(src + 4);
        }
        __syncthreads();
        #pragma unroll
        for (int k = 0; k < 16; ++k) {
            float4 a  = *(const float4*)(sAH + (kk + k) * SA + m * 4);
            float4 w0 = *(const float4*)(sB + k * 128 + g * 8);
            float4 w1 = *(const float4*)(sB + k * 128 + g * 8 + 4);
            float av[4] = {a.x, a.y, a.z, a.w};
            float wv[8] = {w0.x, w0.y, w0.z, w0.w, w1.x, w1.y, w1.z, w1.w};
            #pragma unroll
            for (int i = 0; i < 4; ++i)
                #pragma unroll
                for (int j = 0; j < 8; ++j)
                    acc[i][j] = fmaf(av[i], wv[j], acc[i][j]);
        }
        __syncthreads();
    }

    #pragma unroll
    for (int j = 0; j < 8; ++j) {
        int h = g * 8 + j;
        float4 v;
        v.x = fmaxf(acc[0][j], 0.0f);
        v.y = fmaxf(acc[1][j], 0.0f);
        v.z = fmaxf(acc[2][j], 0.0f);
        v.w = fmaxf(acc[3][j], 0.0f);
        *(float4*)(sAH + h * SA + m * 4) = v;
    }
    __syncthreads();

    float acc2[4][8];
    {
        float4 b0 = *(const float4*)(bh2 + g * 8);
        float4 b1 = *(const float4*)(bh2 + g * 8 + 4);
        #pragma unroll
        for (int i = 0; i < 4; ++i) {
            acc2[i][0] = b0.x; acc2[i][1] = b0.y; acc2[i][2] = b0.z; acc2[i][3] = b0.w;
            acc2[i][4] = b1.x; acc2[i][5] = b1.y; acc2[i][6] = b1.z; acc2[i][7] = b1.w;
        }
    }

    for (int kk = 0; kk < 128; kk += 16) {
        {
            int idx = t * 8;
            int r   = idx >> 7;
            int cc  = idx & 127;
            const float* src = Wh2 + (size_t)(kk + r) * Fdim + cc;
            *(float4*)(sB + idx)     = *(const float4*)src;
            *(float4*)(sB + idx + 4) = *(const float4*)(src + 4);
        }
        __syncthreads();
        #pragma unroll
        for (int k = 0; k < 16; ++k) {
            float4 a  = *(const float4*)(sAH + (kk + k) * SA + m * 4);
            float4 w0 = *(const float4*)(sB + k * 128 + g * 8);
            float4 w1 = *(const float4*)(sB + k * 128 + g * 8 + 4);
            float av[4] = {a.x, a.y, a.z, a.w};
            float wv[8] = {w0.x, w0.y, w0.z, w0.w, w1.x, w1.y, w1.z, w1.w};
            #pragma unroll
            for (int i = 0; i < 4; ++i)
                #pragma unroll
                for (int j = 0; j < 8; ++j)
                    acc2[i][j] = fmaf(av[i], wv[j], acc2[i][j]);
        }
        __syncthreads();
    }

    #pragma unroll
    for (int i = 0; i < 4; ++i) {
        int row = r0 + m * 4 + i;
        if (row < N) {
            float4 v0, v1;
            v0.x = acc2[i][0]; v0.y = acc2[i][1]; v0.z = acc2[i][2]; v0.w = acc2[i][3];
            v1.x = acc2[i][4]; v1.y = acc2[i][5]; v1.z = acc2[i][6]; v1.w = acc2[i][7];
            *(float4*)(outH + (size_t)row * Fdim + g * 8)     = v0;
            *(float4*)(outH + (size_t)row * Fdim + g * 8 + 4) = v1;
        }
    }
}

// ---------------- coordinate update -----------------------------------------
__global__ void x_kernel(const float* __restrict__ coord,
                         float* __restrict__ outX,
                         int n3, float C)
{
    int i = blockIdx.x * blockDim.x + threadIdx.x;
    if (i < n3) {
        int n = i / 3, d = i - n * 3;
        outX[i] = coord[i] + g_dx4[(size_t)n * 4 + d] * C;
    }
}

// ---------------- launch -----------------------------------------------------
extern "C" void kernel_launch(void* const* d_in, const int* in_sizes, int n_in,
                              void* d_out, int out_size)
{
    const float* node  = (const float*)d_in[0];
    const float* coord = (const float*)d_in[1];
    const int*   ei    = (const int*)d_in[2];
    const float* We1   = (const float*)d_in[3];
    const float* be1   = (const float*)d_in[4];
    const float* We2   = (const float*)d_in[5];
    const float* be2   = (const float*)d_in[6];
    const float* Wx    = (const float*)d_in[7];
    const float* bx    = (const float*)d_in[8];
    const float* Wh1   = (const float*)d_in[9];
    const float* bh1   = (const float*)d_in[10];
    const float* Wh2   = (const float*)d_in[11];
    const float* bh2   = (const float*)d_in[12];

    const int N = in_sizes[0] / Fdim;
    const int E = in_sizes[2] / 2;

    float* outH = (float*)d_out;
    float* outX = outH + (size_t)N * Fdim;

    const int node_smem = (256 * SA + 16 * 128) * 4;
    cudaFuncSetAttribute(edge_kernel, cudaFuncAttributeMaxDynamicSharedMemorySize, EDGE_SMEM);
    cudaFuncSetAttribute(node_kernel, cudaFuncAttributeMaxDynamicSharedMemorySize, node_smem);

    prep_kernel<<<(49152 + 255) / 256, 256>>>(We1, We2);
    {
        int n_mi = N * 128;
        zero_kernel<<<(n_mi + 255) / 256, 256>>>(n_mi, N * 4);
    }
    {
        int grid = (E + ET - 1) / ET;
        edge_kernel<<<grid, 256, EDGE_SMEM>>>(node, coord, ei, We1, be1, be2, Wx, bx, E);
    }
    {
        int grid = (N + TILE - 1) / TILE;
        node_kernel<<<grid, NTHREADS, node_smem>>>(node, Wh1, bh1, Wh2, bh2, outH, N);
    }
    {
        int n3 = N * 3;
        float C = 1.0f / (float)(N - 1);
        x_kernel<<<(n3 + 255) / 256, 256>>>(coord, outX, n3, C);
    }
}

// round 4
// speedup vs baseline: 1.4495x; 1.0307x over previous
#include <cuda_runtime.h>
#include <cuda_bf16.h>
#include <cstdint>

#define Fdim 128
#define ET   128              // edges per tile (MMA M)
#define MAXN 50000
#define TILE 64               // node-kernel row tile
#define NTHREADS 256
#define SA 72                 // node-kernel fp32 padded stride
#define SAB 72                // edge-kernel bf16 padded stride (144 B rows)

// ---------------- scratch (static device arrays; allocation-free) ----------
__device__ float g_mi[(size_t)MAXN * 128];
__device__ float g_dx4[(size_t)MAXN * 4];
// pre-split padded weight images: [chunk][ hi(128*72) | lo(128*72) ] bf16, [n][k]
__device__ __align__(16) __nv_bfloat16 gB1[4][2 * 128 * SAB];
__device__ __align__(16) __nv_bfloat16 gB2[2][2 * 128 * SAB];

#define BCHUNK (2 * 128 * SAB * 2)   /* 36864 bytes per panel (hi+lo) */

// ---------------- PTX helpers ----------------------------------------------
__device__ __forceinline__ uint32_t smem_u32(const void* p) {
    uint32_t a;
    asm("{ .reg .u64 t; cvta.to.shared.u64 t, %1; cvt.u32.u64 %0, t; }" : "=r"(a) : "l"(p));
    return a;
}

#define LDSM4(r0, r1, r2, r3, addr) \
    asm volatile("ldmatrix.sync.aligned.m8n8.x4.shared.b16 {%0,%1,%2,%3}, [%4];" \
                 : "=r"(r0), "=r"(r1), "=r"(r2), "=r"(r3) : "r"(addr))

#define MMA16816(cp, a0, a1, a2, a3, b0, b1) \
    asm volatile("mma.sync.aligned.m16n8k16.row.col.f32.bf16.bf16.f32 " \
                 "{%0,%1,%2,%3},{%4,%5,%6,%7},{%8,%9},{%0,%1,%2,%3};" \
                 : "+f"((cp)[0]), "+f"((cp)[1]), "+f"((cp)[2]), "+f"((cp)[3]) \
                 : "r"(a0), "r"(a1), "r"(a2), "r"(a3), "r"(b0), "r"(b1))

#define MB_INIT(mb, c) asm volatile("mbarrier.init.shared.b64 [%0], %1;" :: "r"(mb), "r"(c) : "memory")
#define MB_EXPECT(mb, b) asm volatile("mbarrier.arrive.expect_tx.shared.b64 _, [%0], %1;" :: "r"(mb), "r"(b) : "memory")
#define BULK_G2S(dst, src, bytes, mb) \
    asm volatile("cp.async.bulk.shared::cluster.global.mbarrier::complete_tx::bytes [%0], [%1], %2, [%3];" \
                 :: "r"(dst), "l"(src), "r"(bytes), "r"(mb) : "memory")

__device__ __forceinline__ void mb_wait(uint32_t mb, uint32_t parity) {
    uint32_t done;
    asm volatile("{ .reg .pred p; mbarrier.try_wait.parity.acquire.cta.shared::cta.b64 p, [%1], %2; selp.b32 %0, 1, 0, p; }"
                 : "=r"(done) : "r"(mb), "r"(parity) : "memory");
    if (!done) {
        asm volatile("{ .reg .pred P1;\nW%=:\n mbarrier.try_wait.parity.acquire.cta.shared::cta.b64 P1, [%0], %1, 0x989680;\n @P1 bra.uni D%=;\n bra.uni W%=;\nD%=:\n}"
                     :: "r"(mb), "r"(parity) : "memory");
    }
}

__device__ __forceinline__ void red2(float* p, float x, float y) {
    asm volatile("red.global.add.v2.f32 [%0], {%1,%2};" :: "l"(p), "f"(x), "f"(y) : "memory");
}
__device__ __forceinline__ void red4(float* p, float4 v) {
    asm volatile("red.global.add.v4.f32 [%0], {%1,%2,%3,%4};"
                 :: "l"(p), "f"(v.x), "f"(v.y), "f"(v.z), "f"(v.w) : "memory");
}

// pack two floats -> bf16x2 (lower = a, upper = b)
__device__ __forceinline__ uint32_t packbf2(float a, float b) {
    uint32_t r;
    asm("cvt.rn.bf16x2.f32 %0, %1, %2;" : "=r"(r) : "f"(b), "f"(a));
    return r;
}

// split 8 floats into hi/lo bf16x2 quads
__device__ __forceinline__ void split8(const float* v, uint4& H, uint4& L) {
    uint32_t h[4], l[4];
    #pragma unroll
    for (int i = 0; i < 4; ++i) {
        float a = v[2 * i], b = v[2 * i + 1];
        uint32_t hp = packbf2(a, b);
        float ah = __uint_as_float(hp << 16);
        float bh = __uint_as_float(hp & 0xFFFF0000u);
        h[i] = hp;
        l[i] = packbf2(a - ah, b - bh);
    }
    H = make_uint4(h[0], h[1], h[2], h[3]);
    L = make_uint4(l[0], l[1], l[2], l[3]);
}

// ---------------- prep: split weights into padded [n][k] images -------------
__global__ void prep_kernel(const float* __restrict__ We1, const float* __restrict__ We2)
{
    int id = blockIdx.x * blockDim.x + threadIdx.x;
    if (id < 32768) {                       // B1: 4 chunks x 128 n x 64 k
        int c   = id >> 13;
        int rem = id & 8191;
        int n   = rem >> 6;
        int kc  = rem & 63;
        float v = We1[(size_t)(c * 64 + kc) * 128 + n];
        __nv_bfloat16 hi = __float2bfloat16(v);
        float lo = v - __bfloat162float(hi);
        gB1[c][n * SAB + kc]              = hi;
        gB1[c][128 * SAB + n * SAB + kc]  = __float2bfloat16(lo);
    } else if (id < 49152) {                // B2: 2 chunks
        int id2 = id - 32768;
        int c   = id2 >> 13;
        int rem = id2 & 8191;
        int n   = rem >> 6;
        int kc  = rem & 63;
        float v = We2[(size_t)(c * 64 + kc) * 128 + n];
        __nv_bfloat16 hi = __float2bfloat16(v);
        float lo = v - __bfloat162float(hi);
        gB2[c][n * SAB + kc]              = hi;
        gB2[c][128 * SAB + n * SAB + kc]  = __float2bfloat16(lo);
    }
}

// ---------------- zero scratch ----------------------------------------------
__global__ void zero_kernel(int n_mi, int n_dx)
{
    int i = blockIdx.x * blockDim.x + threadIdx.x;
    if (i < n_mi) g_mi[i] = 0.0f;
    if (i < n_dx) g_dx4[i] = 0.0f;
}

// ---------------- edge kernel: mma.sync split-bf16 + bulk-async B ----------
// SMEM layout (bytes):
#define SO_A0   0          /* A buf0: hi 18432 | lo 18432 */
#define SO_A1   36864
#define SO_B0   73728      /* B buf0: hi 18432 | lo 18432 */
#define SO_B1   110592
#define SO_DS   147456     /* float4[128] */
#define SO_W    149504     /* float[128] */
#define SO_DST  150016     /* int[128] */
#define SO_WX   150528
#define SO_BE1  151040
#define SO_BE2  151552
#define SO_W256 152064
#define SO_MB   152576     /* 2 mbarriers */
#define EDGE_SMEM 152704

__global__ __launch_bounds__(256, 1)
void edge_kernel(const float* __restrict__ node,
                 const float* __restrict__ coord,
                 const int*   __restrict__ ei,
                 const float* __restrict__ We1,
                 const float* __restrict__ be1,
                 const float* __restrict__ be2,
                 const float* __restrict__ Wx,
                 const float* __restrict__ bxp,
                 int E)
{
    extern __shared__ char sm[];
    const uint32_t sbase = smem_u32(sm);

    float4* sDS  = (float4*)(sm + SO_DS);
    float*  sW   = (float*)(sm + SO_W);
    int*    sDst = (int*)(sm + SO_DST);
    float*  sWx  = (float*)(sm + SO_WX);
    float*  sBe1 = (float*)(sm + SO_BE1);
    float*  sBe2 = (float*)(sm + SO_BE2);
    float*  sW256= (float*)(sm + SO_W256);

    const int t    = threadIdx.x;
    const int wid  = t >> 5;
    const int lane = t & 31;
    const int e0   = blockIdx.x * ET;
    const float bx = bxp[0];

    const uint32_t mb0 = sbase + SO_MB;
    const uint32_t mb1 = sbase + SO_MB + 8;

    if (t == 0) { MB_INIT(mb0, 1); MB_INIT(mb1, 1); }

    // ---- per-edge metadata ----
    if (t < ET) {
        int eg = e0 + t;
        float dx = 0.f, dy = 0.f, dz = 0.f;
        int di = -1;
        if (eg < E) {
            int si = ei[eg];
            di     = ei[E + eg];
            dx = coord[(size_t)di * 3 + 0] - coord[(size_t)si * 3 + 0];
            dy = coord[(size_t)di * 3 + 1] - coord[(size_t)si * 3 + 1];
            dz = coord[(size_t)di * 3 + 2] - coord[(size_t)si * 3 + 2];
        }
        sDS[t]  = make_float4(dx, dy, dz, dx * dx + dy * dy + dz * dz);
        sDst[t] = di;
        sWx[t]  = Wx[t];
        sBe1[t] = be1[t];
        sBe2[t] = be2[t];
        sW256[t]= We1[(size_t)256 * 128 + t];
    }
    __syncthreads();            // mbarriers init'd + metadata visible

    // kick off first two B panel copies
    if (t == 0) {
        MB_EXPECT(mb0, BCHUNK);
        BULK_G2S(sbase + SO_B0, (const void*)gB1[0], BCHUNK, mb0);
        MB_EXPECT(mb1, BCHUNK);
        BULK_G2S(sbase + SO_B1, (const void*)gB1[1], BCHUNK, mb1);
    }

    // gather role: thread covers row = t/2, cols half*32..+31
    const int grow = t >> 1;
    const int ghalf = t & 1;
    int gsi = 0, gdi = 0;
    bool gvalid = (e0 + grow) < E;
    if (gvalid) { gsi = ei[e0 + grow]; gdi = ei[E + e0 + grow]; }

    // ldmatrix lane addressing
    const int seg = lane >> 3, ln = lane & 7;
    const uint32_t aoff = (uint32_t)((wid * 16 + ln + ((seg & 1) << 3)) * 144 + (((seg >> 1) & 1) << 4));
    const uint32_t boff0 = (uint32_t)((ln + ((seg >> 1) << 3)) * 144 + ((seg & 1) << 4));
    const uint32_t a_ab  = (uint32_t)(grow * 144 + ghalf * 64);

    // ---- A staging helper (gather + split into buffer b) ----
    auto stageA = [&](int c, uint32_t abo) {
        const float* rp = node + (size_t)(c < 2 ? gdi : gsi) * 128 + (c & 1) * 64 + ghalf * 32;
        #pragma unroll
        for (int u = 0; u < 4; ++u) {
            float v[8];
            if (gvalid) {
                float4 v0 = *(const float4*)(rp + u * 8);
                float4 v1 = *(const float4*)(rp + u * 8 + 4);
                v[0]=v0.x; v[1]=v0.y; v[2]=v0.z; v[3]=v0.w;
                v[4]=v1.x; v[5]=v1.y; v[6]=v1.z; v[7]=v1.w;
            } else {
                #pragma unroll
                for (int q = 0; q < 8; ++q) v[q] = 0.0f;
            }
            uint4 H, L;
            split8(v, H, L);
            *(uint4*)(sm + abo + a_ab + u * 16)         = H;
            *(uint4*)(sm + abo + a_ab + u * 16 + 18432) = L;
        }
    };

    float c1[64];
    #pragma unroll
    for (int i = 0; i < 64; ++i) c1[i] = 0.0f;

    // stage A chunk 0 into A buf 0
    stageA(0, SO_A0);
    __syncthreads();

    uint32_t ph0 = 0, ph1 = 0;

    // ================= GEMM1: 4 k-chunks of 64, double-buffered =============
    #pragma unroll 1
    for (int c = 0; c < 4; ++c) {
        const uint32_t ab = (c & 1) ? SO_A1 : SO_A0;
        const uint32_t bb = (c & 1) ? SO_B1 : SO_B0;

        if (c < 3) stageA(c + 1, (c & 1) ? SO_A0 : SO_A1);

        // wait for this chunk's B panel
        if (c & 1) { mb_wait(mb1, ph1); ph1 ^= 1; }
        else       { mb_wait(mb0, ph0); ph0 ^= 1; }

        #pragma unroll
        for (int ks = 0; ks < 4; ++ks) {
            uint32_t ah0,ah1,ah2,ah3, al0,al1,al2,al3;
            LDSM4(ah0,ah1,ah2,ah3, sbase + ab + aoff + ks * 32);
            LDSM4(al0,al1,al2,al3, sbase + ab + 18432 + aoff + ks * 32);
            #pragma unroll
            for (int jb = 0; jb < 8; ++jb) {
                uint32_t bo = boff0 + (uint32_t)(jb * 16 * 144 + ks * 32);
                uint32_t bh0,bh1,bh2,bh3, bl0,bl1,bl2,bl3;
                LDSM4(bh0,bh1,bh2,bh3, sbase + bb + bo);
                LDSM4(bl0,bl1,bl2,bl3, sbase + bb + 18432 + bo);
                float* cp0 = c1 + 8 * jb;
                float* cp1 = c1 + 8 * jb + 4;
                MMA16816(cp0, ah0,ah1,ah2,ah3, bh0,bh1);
                MMA16816(cp0, ah0,ah1,ah2,ah3, bl0,bl1);
                MMA16816(cp0, al0,al1,al2,al3, bh0,bh1);
                MMA16816(cp1, ah0,ah1,ah2,ah3, bh2,bh3);
                MMA16816(cp1, ah0,ah1,ah2,ah3, bl2,bl3);
                MMA16816(cp1, al0,al1,al2,al3, bh2,bh3);
            }
        }
        __syncthreads();      // all warps done with this B buf + next A staged

        if (t == 0) {         // refill the just-freed B buffer
            const void* nsrc = (c == 0) ? (const void*)gB1[2]
                             : (c == 1) ? (const void*)gB1[3]
                             : (c == 2) ? (const void*)gB2[0]
                                        : (const void*)gB2[1];
            uint32_t dst = (c & 1) ? (sbase + SO_B1) : (sbase + SO_B0);
            uint32_t mb  = (c & 1) ? mb1 : mb0;
            MB_EXPECT(mb, BCHUNK);
            BULK_G2S(dst, nsrc, BCHUNK, mb);
        }
    }

    // ============ epilogue1: relu(c1 + be1 + sqdist * We1[256,:]) ===========
    const int r0 = wid * 16 + (lane >> 2);
    const int q  = lane & 3;
    const float sq0 = sDS[r0].w;
    const float sq1 = sDS[r0 + 8].w;
    #pragma unroll
    for (int f = 0; f < 16; ++f) {
        int col = 8 * f + 2 * q;
        float2 b = *(float2*)(sBe1 + col);
        float2 w = *(float2*)(sW256 + col);
        c1[4*f+0] = fmaxf(c1[4*f+0] + b.x + sq0 * w.x, 0.0f);
        c1[4*f+1] = fmaxf(c1[4*f+1] + b.y + sq0 * w.y, 0.0f);
        c1[4*f+2] = fmaxf(c1[4*f+2] + b.x + sq1 * w.x, 0.0f);
        c1[4*f+3] = fmaxf(c1[4*f+3] + b.y + sq1 * w.y, 0.0f);
    }

    // ================= GEMM2: hidden @ We2 (A from registers) ===============
    float c2[64];
    #pragma unroll
    for (int i = 0; i < 64; ++i) c2[i] = 0.0f;

    #pragma unroll 1
    for (int r = 0; r < 2; ++r) {
        const uint32_t bb = r ? SO_B1 : SO_B0;
        if (r) { mb_wait(mb1, ph1); ph1 ^= 1; }
        else   { mb_wait(mb0, ph0); ph0 ^= 1; }

        #pragma unroll
        for (int ks = 0; ks < 4; ++ks) {
            const int f0 = r * 8 + ks * 2;
            uint32_t ah[4], al[4];
            #pragma unroll
            for (int i = 0; i < 4; ++i) {
                float va = c1[4 * f0 + 2 * i];
                float vb = c1[4 * f0 + 2 * i + 1];
                uint32_t hp = packbf2(va, vb);
                ah[i] = hp;
                float ea = __uint_as_float(hp << 16);
                float eb = __uint_as_float(hp & 0xFFFF0000u);
                al[i] = packbf2(va - ea, vb - eb);
            }
            #pragma unroll
            for (int jb = 0; jb < 8; ++jb) {
                uint32_t bo = boff0 + (uint32_t)(jb * 16 * 144 + ks * 32);
                uint32_t bh0,bh1,bh2,bh3, bl0,bl1,bl2,bl3;
                LDSM4(bh0,bh1,bh2,bh3, sbase + bb + bo);
                LDSM4(bl0,bl1,bl2,bl3, sbase + bb + 18432 + bo);
                float* cp0 = c2 + 8 * jb;
                float* cp1 = c2 + 8 * jb + 4;
                MMA16816(cp0, ah[0],ah[1],ah[2],ah[3], bh0,bh1);
                MMA16816(cp0, ah[0],ah[1],ah[2],ah[3], bl0,bl1);
                MMA16816(cp0, al[0],al[1],al[2],al[3], bh0,bh1);
                MMA16816(cp1, ah[0],ah[1],ah[2],ah[3], bh2,bh3);
                MMA16816(cp1, ah[0],ah[1],ah[2],ah[3], bl2,bl3);
                MMA16816(cp1, al[0],al[1],al[2],al[3], bh2,bh3);
            }
        }
    }

    // ============ epilogue2: bias, scalar head, register-direct scatter =====
    const int dst0 = sDst[r0];
    const int dst1 = sDst[r0 + 8];
    float w0 = 0.0f, w1 = 0.0f;
    #pragma unroll
    for (int f = 0; f < 16; ++f) {
        int col = 8 * f + 2 * q;
        float2 b  = *(float2*)(sBe2 + col);
        float2 wx = *(float2*)(sWx + col);
        float v0 = c2[4*f+0] + b.x;
        float v1 = c2[4*f+1] + b.y;
        float v2 = c2[4*f+2] + b.x;
        float v3 = c2[4*f+3] + b.y;
        w0 = fmaf(v0, wx.x, fmaf(v1, wx.y, w0));
        w1 = fmaf(v2, wx.x, fmaf(v3, wx.y, w1));
        if (dst0 >= 0) red2(g_mi + (size_t)dst0 * 128 + col, v0, v1);
        if (dst1 >= 0) red2(g_mi + (size_t)dst1 * 128 + col, v2, v3);
    }
    // quad reduction for edge weights
    w0 += __shfl_xor_sync(0xffffffffu, w0, 1);
    w0 += __shfl_xor_sync(0xffffffffu, w0, 2);
    w1 += __shfl_xor_sync(0xffffffffu, w1, 1);
    w1 += __shfl_xor_sync(0xffffffffu, w1, 2);
    if (q == 0) {
        sW[r0]     = w0 + bx;
        sW[r0 + 8] = w1 + bx;
    }
    __syncthreads();

    if (t < ET) {
        int di = sDst[t];
        if (di >= 0) {
            float w = sW[t];
            float4 ds = sDS[t];
            red4(g_dx4 + (size_t)di * 4, make_float4(ds.x * w, ds.y * w, ds.z * w, 0.0f));
        }
    }
}

// ---------------- node kernel (round-1 FFMA, proven) ------------------------
__global__ __launch_bounds__(NTHREADS, 2)
void node_kernel(const float* __restrict__ node,
                 const float* __restrict__ Wh1,
                 const float* __restrict__ bh1,
                 const float* __restrict__ Wh2,
                 const float* __restrict__ bh2,
                 float* __restrict__ outH,
                 int N)
{
    extern __shared__ float s[];
    float* sAH = s;
    float* sB  = s + 256 * SA;

    const int t  = threadIdx.x;
    const int r0 = blockIdx.x * TILE;

    {
        int n   = t & 63;
        int c   = t >> 6;
        int row = r0 + n;
        if (row < N) {
            const float* srow = (c < 2) ? (node + (size_t)row * Fdim + c * 64)
                                        : (g_mi + (size_t)row * 128 + (c - 2) * 64);
            int kb = c * 64;
            #pragma unroll
            for (int r = 0; r < 16; ++r) {
                float4 v = *(const float4*)(srow + r * 4);
                int k = kb + r * 4;
                sAH[(k + 0) * SA + n] = v.x;
                sAH[(k + 1) * SA + n] = v.y;
                sAH[(k + 2) * SA + n] = v.z;
                sAH[(k + 3) * SA + n] = v.w;
            }
        }
    }
    __syncthreads();

    const int m = t & 15;
    const int g = t >> 4;

    float acc[4][8];
    {
        float4 b0 = *(const float4*)(bh1 + g * 8);
        float4 b1 = *(const float4*)(bh1 + g * 8 + 4);
        #pragma unroll
        for (int i = 0; i < 4; ++i) {
            acc[i][0] = b0.x; acc[i][1] = b0.y; acc[i][2] = b0.z; acc[i][3] = b0.w;
            acc[i][4] = b1.x; acc[i][5] = b1.y; acc[i][6] = b1.z; acc[i][7] = b1.w;
        }
    }

    for (int kk = 0; kk < 256; kk += 16) {
        {
            int idx = t * 8;
            int r   = idx >> 7;
            int cc  = idx & 127;
            const float* src = Wh1 + (size_t)(kk + r) * 128 + cc;
            *(float4*)(sB + idx)     = *(const float4*)src;
            *(float4*)(sB + idx + 4) = *(const float4*)(src + 4);
        }
        __syncthreads();
        #pragma unroll
        for (int k = 0; k < 16; ++k) {
            float4 a  = *(const float4*)(sAH + (kk + k) * SA + m * 4);
            float4 w0 = *(const float4*)(sB + k * 128 + g * 8);
            float4 w1 = *(const float4*)(sB + k * 128 + g * 8 + 4);
            float av[4] = {a.x, a.y, a.z, a.w};
            float wv[8] = {w0.x, w0.y, w0.z, w0.w, w1.x, w1.y, w1.z, w1.w};
            #pragma unroll
            for (int i = 0; i < 4; ++i)
                #pragma unroll
                for (int j = 0; j < 8; ++j)
                    acc[i][j] = fmaf(av[i], wv[j], acc[i][j]);
        }
        __syncthreads();
    }

    #pragma unroll
    for (int j = 0; j < 8; ++j) {
        int h = g * 8 + j;
        float4 v;
        v.x = fmaxf(acc[0][j], 0.0f);
        v.y = fmaxf(acc[1][j], 0.0f);
        v.z = fmaxf(acc[2][j], 0.0f);
        v.w = fmaxf(acc[3][j], 0.0f);
        *(float4*)(sAH + h * SA + m * 4) = v;
    }
    __syncthreads();

    float acc2[4][8];
    {
        float4 b0 = *(const float4*)(bh2 + g * 8);
        float4 b1 = *(const float4*)(bh2 + g * 8 + 4);
        #pragma unroll
        for (int i = 0; i < 4; ++i) {
            acc2[i][0] = b0.x; acc2[i][1] = b0.y; acc2[i][2] = b0.z; acc2[i][3] = b0.w;
            acc2[i][4] = b1.x; acc2[i][5] = b1.y; acc2[i][6] = b1.z; acc2[i][7] = b1.w;
        }
    }

    for (int kk = 0; kk < 128; kk += 16) {
        {
            int idx = t * 8;
            int r   = idx >> 7;
            int cc  = idx & 127;
            const float* src = Wh2 + (size_t)(kk + r) * Fdim + cc;
            *(float4*)(sB + idx)     = *(const float4*)src;
            *(float4*)(sB + idx + 4) = *(const float4*)(src + 4);
        }
        __syncthreads();
        #pragma unroll
        for (int k = 0; k < 16; ++k) {
            float4 a  = *(const float4*)(sAH + (kk + k) * SA + m * 4);
            float4 w0 = *(const float4*)(sB + k * 128 + g * 8);
            float4 w1 = *(const float4*)(sB + k * 128 + g * 8 + 4);
            float av[4] = {a.x, a.y, a.z, a.w};
            float wv[8] = {w0.x, w0.y, w0.z, w0.w, w1.x, w1.y, w1.z, w1.w};
            #pragma unroll
            for (int i = 0; i < 4; ++i)
                #pragma unroll
                for (int j = 0; j < 8; ++j)
                    acc2[i][j] = fmaf(av[i], wv[j], acc2[i][j]);
        }
        __syncthreads();
    }

    #pragma unroll
    for (int i = 0; i < 4; ++i) {
        int row = r0 + m * 4 + i;
        if (row < N) {
            float4 v0, v1;
            v0.x = acc2[i][0]; v0.y = acc2[i][1]; v0.z = acc2[i][2]; v0.w = acc2[i][3];
            v1.x = acc2[i][4]; v1.y = acc2[i][5]; v1.z = acc2[i][6]; v1.w = acc2[i][7];
            *(float4*)(outH + (size_t)row * Fdim + g * 8)     = v0;
            *(float4*)(outH + (size_t)row * Fdim + g * 8 + 4) = v1;
        }
    }
}

// ---------------- coordinate update -----------------------------------------
__global__ void x_kernel(const float* __restrict__ coord,
                         float* __restrict__ outX,
                         int n3, float C)
{
    int i = blockIdx.x * blockDim.x + threadIdx.x;
    if (i < n3) {
        int n = i / 3, d = i - n * 3;
        outX[i] = coord[i] + g_dx4[(size_t)n * 4 + d] * C;
    }
}

// ---------------- launch -----------------------------------------------------
extern "C" void kernel_launch(void* const* d_in, const int* in_sizes, int n_in,
                              void* d_out, int out_size)
{
    const float* node  = (const float*)d_in[0];
    const float* coord = (const float*)d_in[1];
    const int*   ei    = (const int*)d_in[2];
    const float* We1   = (const float*)d_in[3];
    const float* be1   = (const float*)d_in[4];
    const float* We2   = (const float*)d_in[5];
    const float* be2   = (const float*)d_in[6];
    const float* Wx    = (const float*)d_in[7];
    const float* bx    = (const float*)d_in[8];
    const float* Wh1   = (const float*)d_in[9];
    const float* bh1   = (const float*)d_in[10];
    const float* Wh2   = (const float*)d_in[11];
    const float* bh2   = (const float*)d_in[12];

    const int N = in_sizes[0] / Fdim;
    const int E = in_sizes[2] / 2;

    float* outH = (float*)d_out;
    float* outX = outH + (size_t)N * Fdim;

    const int node_smem = (256 * SA + 16 * 128) * 4;
    cudaFuncSetAttribute(edge_kernel, cudaFuncAttributeMaxDynamicSharedMemorySize, EDGE_SMEM);
    cudaFuncSetAttribute(node_kernel, cudaFuncAttributeMaxDynamicSharedMemorySize, node_smem);

    prep_kernel<<<(49152 + 255) / 256, 256>>>(We1, We2);
    {
        int n_mi = N * 128;
        zero_kernel<<<(n_mi + 255) / 256, 256>>>(n_mi, N * 4);
    }
    {
        int grid = (E + ET - 1) / ET;
        edge_kernel<<<grid, 256, EDGE_SMEM>>>(node, coord, ei, We1, be1, be2, Wx, bx, E);
    }
    {
        int grid = (N + TILE - 1) / TILE;
        node_kernel<<<grid, NTHREADS, node_smem>>>(node, Wh1, bh1, Wh2, bh2, outH, N);
    }
    {
        int n3 = N * 3;
        float C = 1.0f / (float)(N - 1);
        x_kernel<<<(n3 + 255) / 256, 256>>>(coord, outX, n3, C);
    }
}

// round 5
// speedup vs baseline: 2.2723x; 1.5676x over previous
#include <cuda_runtime.h>
#include <cuda_bf16.h>
#include <cstdint>

#define Fdim 128
#define ET2  256              // edges per CTA tile (MMA M)
#define MAXN 50000
#define TILE 64               // node-kernel row tile
#define NTHREADS 256
#define SA 72                 // node-kernel fp32 padded stride

// ---------------- scratch (static device arrays; allocation-free) ----------
__device__ float g_mi[(size_t)MAXN * 128];
__device__ float g_dx4[(size_t)MAXN * 4];
// pre-split swizzled weight chunk images: [hi 8192 | lo 8192] bf16, rows=n(128), kc(64)
__device__ __align__(16) __nv_bfloat16 gB1[4][16384];
__device__ __align__(16) __nv_bfloat16 gB2[2][16384];

#define BCH 32768            /* bytes per B chunk (hi+lo) */

// ---------------- PTX helpers ----------------------------------------------
__device__ __forceinline__ uint32_t smem_u32(const void* p) {
    uint32_t a;
    asm("{ .reg .u64 t; cvta.to.shared.u64 t, %1; cvt.u32.u64 %0, t; }" : "=r"(a) : "l"(p));
    return a;
}

#define LDSM4(r0, r1, r2, r3, addr) \
    asm volatile("ldmatrix.sync.aligned.m8n8.x4.shared.b16 {%0,%1,%2,%3}, [%4];" \
                 : "=r"(r0), "=r"(r1), "=r"(r2), "=r"(r3) : "r"(addr))

#define MMA16816(cp, a0, a1, a2, a3, b0, b1) \
    asm volatile("mma.sync.aligned.m16n8k16.row.col.f32.bf16.bf16.f32 " \
                 "{%0,%1,%2,%3},{%4,%5,%6,%7},{%8,%9},{%0,%1,%2,%3};" \
                 : "+f"((cp)[0]), "+f"((cp)[1]), "+f"((cp)[2]), "+f"((cp)[3]) \
                 : "r"(a0), "r"(a1), "r"(a2), "r"(a3), "r"(b0), "r"(b1))

#define MB_INIT(mb, c) asm volatile("mbarrier.init.shared.b64 [%0], %1;" :: "r"(mb), "r"(c) : "memory")
#define MB_EXPECT(mb, b) asm volatile("mbarrier.arrive.expect_tx.shared.b64 _, [%0], %1;" :: "r"(mb), "r"(b) : "memory")
#define BULK_G2S(dst, src, bytes, mb) \
    asm volatile("cp.async.bulk.shared::cluster.global.mbarrier::complete_tx::bytes [%0], [%1], %2, [%3];" \
                 :: "r"(dst), "l"(src), "r"(bytes), "r"(mb) : "memory")

__device__ __forceinline__ void mb_wait(uint32_t mb, uint32_t parity) {
    uint32_t done;
    asm volatile("{ .reg .pred p; mbarrier.try_wait.parity.acquire.cta.shared::cta.b64 p, [%1], %2; selp.b32 %0, 1, 0, p; }"
                 : "=r"(done) : "r"(mb), "r"(parity) : "memory");
    if (!done) {
        asm volatile("{ .reg .pred P1;\nW%=:\n mbarrier.try_wait.parity.acquire.cta.shared::cta.b64 P1, [%0], %1, 0x989680;\n @P1 bra.uni D%=;\n bra.uni W%=;\nD%=:\n}"
                     :: "r"(mb), "r"(parity) : "memory");
    }
}

__device__ __forceinline__ void red2(float* p, float x, float y) {
    asm volatile("red.global.add.v2.f32 [%0], {%1,%2};" :: "l"(p), "f"(x), "f"(y) : "memory");
}
__device__ __forceinline__ void red4(float* p, float4 v) {
    asm volatile("red.global.add.v4.f32 [%0], {%1,%2,%3,%4};"
                 :: "l"(p), "f"(v.x), "f"(v.y), "f"(v.z), "f"(v.w) : "memory");
}

// pack two floats -> bf16x2 (lower = a, upper = b)
__device__ __forceinline__ uint32_t packbf2(float a, float b) {
    uint32_t r;
    asm("cvt.rn.bf16x2.f32 %0, %1, %2;" : "=r"(r) : "f"(b), "f"(a));
    return r;
}

// split 8 floats into hi/lo bf16x2 quads
__device__ __forceinline__ void split8(const float* v, uint4& H, uint4& L) {
    uint32_t h[4], l[4];
    #pragma unroll
    for (int i = 0; i < 4; ++i) {
        float a = v[2 * i], b = v[2 * i + 1];
        uint32_t hp = packbf2(a, b);
        float ah = __uint_as_float(hp << 16);
        float bh = __uint_as_float(hp & 0xFFFF0000u);
        h[i] = hp;
        l[i] = packbf2(a - ah, b - bh);
    }
    H = make_uint4(h[0], h[1], h[2], h[3]);
    L = make_uint4(l[0], l[1], l[2], l[3]);
}

// swizzled element offset within a [row][kc] tile, 64 bf16 per row (128 B)
__host__ __device__ __forceinline__ int swoff(int n, int kc) {
    return n * 64 + ((((kc >> 3) ^ (n & 7)) << 3) | (kc & 7));
}

// ---------------- prep: split weights into swizzled chunk images ------------
__global__ void prep_kernel(const float* __restrict__ We1, const float* __restrict__ We2)
{
    int id = blockIdx.x * blockDim.x + threadIdx.x;
    if (id < 32768) {                       // B1: 4 chunks x 128 n x 64 kc
        int c   = id >> 13;
        int rem = id & 8191;
        int n   = rem >> 6;
        int kc  = rem & 63;
        float v = We1[(size_t)(c * 64 + kc) * 128 + n];
        __nv_bfloat16 hi = __float2bfloat16(v);
        float lo = v - __bfloat162float(hi);
        int o = swoff(n, kc);
        gB1[c][o]        = hi;
        gB1[c][8192 + o] = __float2bfloat16(lo);
    } else if (id < 49152) {                // B2: 2 chunks
        int id2 = id - 32768;
        int c   = id2 >> 13;
        int rem = id2 & 8191;
        int n   = rem >> 6;
        int kc  = rem & 63;
        float v = We2[(size_t)(c * 64 + kc) * 128 + n];
        __nv_bfloat16 hi = __float2bfloat16(v);
        float lo = v - __bfloat162float(hi);
        int o = swoff(n, kc);
        gB2[c][o]        = hi;
        gB2[c][8192 + o] = __float2bfloat16(lo);
    }
}

// ---------------- zero scratch ----------------------------------------------
__global__ void zero_kernel(int n_mi, int n_dx)
{
    int i = blockIdx.x * blockDim.x + threadIdx.x;
    if (i < n_mi) g_mi[i] = 0.0f;
    if (i < n_dx) g_dx4[i] = 0.0f;
}

// ---------------- edge kernel ------------------------------------------------
// SMEM layout (bytes): A buffers hold 256 rows x 64 kc, hi then lo (32K each)
#define SO_A0   0
#define SO_A1   65536
#define SO_B0   131072
#define SO_B1   163840
#define SO_DS   196608     /* float4[256] */
#define SO_W    200704     /* float[256] */
#define SO_DST  201728     /* int[256] */
#define SO_WX   202752
#define SO_BE1  203264
#define SO_BE2  203776
#define SO_W256 204288
#define SO_MB   204800
#define EDGE_SMEM 204832

__global__ __launch_bounds__(512, 1)
void edge_kernel(const float* __restrict__ node,
                 const float* __restrict__ coord,
                 const int*   __restrict__ ei,
                 const float* __restrict__ We1,
                 const float* __restrict__ be1,
                 const float* __restrict__ be2,
                 const float* __restrict__ Wx,
                 const float* __restrict__ bxp,
                 int E)
{
    extern __shared__ char sm[];
    const uint32_t sbase = smem_u32(sm);

    float4* sDS  = (float4*)(sm + SO_DS);
    float*  sW   = (float*)(sm + SO_W);
    int*    sDst = (int*)(sm + SO_DST);
    float*  sWx  = (float*)(sm + SO_WX);
    float*  sBe1 = (float*)(sm + SO_BE1);
    float*  sBe2 = (float*)(sm + SO_BE2);
    float*  sW256= (float*)(sm + SO_W256);

    const int t    = threadIdx.x;
    const int wid  = t >> 5;
    const int lane = t & 31;
    const int e0   = blockIdx.x * ET2;
    const float bx = bxp[0];

    const uint32_t mb0 = sbase + SO_MB;
    const uint32_t mb1 = sbase + SO_MB + 8;

    if (t == 0) { MB_INIT(mb0, 1); MB_INIT(mb1, 1); }

    // ---- per-edge metadata ----
    if (t < ET2) {
        int eg = e0 + t;
        float dx = 0.f, dy = 0.f, dz = 0.f;
        int di = -1;
        if (eg < E) {
            int si = ei[eg];
            di     = ei[E + eg];
            dx = coord[(size_t)di * 3 + 0] - coord[(size_t)si * 3 + 0];
            dy = coord[(size_t)di * 3 + 1] - coord[(size_t)si * 3 + 1];
            dz = coord[(size_t)di * 3 + 2] - coord[(size_t)si * 3 + 2];
        }
        sDS[t]  = make_float4(dx, dy, dz, dx * dx + dy * dy + dz * dz);
        sDst[t] = di;
    }
    if (t < 128) {
        sWx[t]  = Wx[t];
        sBe1[t] = be1[t];
        sBe2[t] = be2[t];
        sW256[t]= We1[(size_t)256 * 128 + t];
    }
    __syncthreads();

    // launch first two B chunk copies
    if (t == 0) {
        MB_EXPECT(mb0, BCH);
        BULK_G2S(sbase + SO_B0, (const void*)gB1[0], BCH, mb0);
        MB_EXPECT(mb1, BCH);
        BULK_G2S(sbase + SO_B1, (const void*)gB1[1], BCH, mb1);
    }

    // gather role: 2 threads per edge row
    const int grow  = t >> 1;          // 0..255
    const int ghalf = t & 1;           // which 32-col half
    int gsi = 0, gdi = 0;
    const bool gvalid = (e0 + grow) < E;
    if (gvalid) { gsi = ei[e0 + grow]; gdi = ei[E + e0 + grow]; }
    const uint32_t g_rowoff = (uint32_t)grow * 128;
    const int      g_rx     = grow & 7;

    // stage A chunk c (gather + split + STS, swizzled) into buffer at byte off abo
    auto stageA = [&](int c, uint32_t abo) {
        const float* rp = node + (size_t)(c < 2 ? gdi : gsi) * 128 + (c & 1) * 64 + ghalf * 32;
        #pragma unroll
        for (int u = 0; u < 4; ++u) {
            float v[8];
            if (gvalid) {
                float4 v0 = *(const float4*)(rp + u * 8);
                float4 v1 = *(const float4*)(rp + u * 8 + 4);
                v[0]=v0.x; v[1]=v0.y; v[2]=v0.z; v[3]=v0.w;
                v[4]=v1.x; v[5]=v1.y; v[6]=v1.z; v[7]=v1.w;
            } else {
                #pragma unroll
                for (int q = 0; q < 8; ++q) v[q] = 0.0f;
            }
            uint4 H, L;
            split8(v, H, L);
            uint32_t off = g_rowoff + (uint32_t)(((ghalf * 4 + u) ^ g_rx) << 4);
            *(uint4*)(sm + abo + off)         = H;
            *(uint4*)(sm + abo + 32768 + off) = L;
        }
    };

    // ldmatrix per-thread addressing constants
    const int seg = lane >> 3;
    const int lnx = lane & 7;
    const int sA_r = seg & 1;          // A: +8 rows
    const int sA_g = (seg >> 1) & 1;   // A: +16B group
    const int sB_r = (seg >> 1) & 1;   // B: +8 rows
    const int sB_g = seg & 1;          // B: +16B group
    const uint32_t a_rowoff = (uint32_t)(wid * 16 + lnx + sA_r * 8) * 128;
    const uint32_t b_rowoff = (uint32_t)(lnx + sB_r * 8) * 128;

    // MMA over one 64-k chunk: A at Ab (hi, +32768 lo), B at Bb (hi, +16384 lo)
    auto doChunk = [&](uint32_t Ab, uint32_t Bb, float* cc) {
        #pragma unroll
        for (int ks = 0; ks < 4; ++ks) {
            uint32_t ag = (uint32_t)(((2 * ks) | sA_g) ^ lnx) << 4;
            uint32_t bg = (uint32_t)(((2 * ks) | sB_g) ^ lnx) << 4;
            uint32_t aaddr = sbase + Ab + a_rowoff + ag;
            uint32_t ah0,ah1,ah2,ah3, al0,al1,al2,al3;
            LDSM4(ah0,ah1,ah2,ah3, aaddr);
            LDSM4(al0,al1,al2,al3, aaddr + 32768);
            #pragma unroll
            for (int jb = 0; jb < 8; ++jb) {
                uint32_t baddr = sbase + Bb + b_rowoff + (uint32_t)(jb * 2048) + bg;
                uint32_t bh0,bh1,bh2,bh3, bl0,bl1,bl2,bl3;
                LDSM4(bh0,bh1,bh2,bh3, baddr);
                LDSM4(bl0,bl1,bl2,bl3, baddr + 16384);
                float* cp0 = cc + 8 * jb;
                float* cp1 = cc + 8 * jb + 4;
                MMA16816(cp0, ah0,ah1,ah2,ah3, bh0,bh1);
                MMA16816(cp1, ah0,ah1,ah2,ah3, bh2,bh3);
                MMA16816(cp0, ah0,ah1,ah2,ah3, bl0,bl1);
                MMA16816(cp1, ah0,ah1,ah2,ah3, bl2,bl3);
                MMA16816(cp0, al0,al1,al2,al3, bh0,bh1);
                MMA16816(cp1, al0,al1,al2,al3, bh2,bh3);
            }
        }
    };

    float c1[64];
    #pragma unroll
    for (int i = 0; i < 64; ++i) c1[i] = 0.0f;

    stageA(0, SO_A0);
    __syncthreads();

    uint32_t ph0 = 0, ph1 = 0;

    // ================= GEMM1: 4 k-chunks of 64 ==============================
    #pragma unroll 1
    for (int c = 0; c < 4; ++c) {
        if (c & 1) { mb_wait(mb1, ph1); ph1 ^= 1; }
        else       { mb_wait(mb0, ph0); ph0 ^= 1; }

        if (c < 3) stageA(c + 1, (c & 1) ? SO_A0 : SO_A1);   // writes other A buf

        doChunk((c & 1) ? SO_A1 : SO_A0, (c & 1) ? SO_B1 : SO_B0, c1);
        __syncthreads();

        if (t == 0) {      // refill just-freed B buf with chunk c+2
            const void* nsrc = (c == 0) ? (const void*)gB1[2]
                             : (c == 1) ? (const void*)gB1[3]
                             : (c == 2) ? (const void*)gB2[0]
                                        : (const void*)gB2[1];
            uint32_t dst = (c & 1) ? (sbase + SO_B1) : (sbase + SO_B0);
            uint32_t mb  = (c & 1) ? mb1 : mb0;
            MB_EXPECT(mb, BCH);
            BULK_G2S(dst, nsrc, BCH, mb);
        }
    }

    // ============ epilogue1: relu + rank-1 sqdist + bias -> split to A bufs ==
    const int r0 = wid * 16 + (lane >> 2);
    const int q  = lane & 3;
    const float sq0 = sDS[r0].w;
    const float sq1 = sDS[r0 + 8].w;
    const uint32_t hrow0 = (uint32_t)r0 * 128;
    const int      hrx   = r0 & 7;          // (r0+8)&7 == r0&7
    #pragma unroll
    for (int f = 0; f < 16; ++f) {
        int col = 8 * f + 2 * q;
        float2 b = *(float2*)(sBe1 + col);
        float2 w = *(float2*)(sW256 + col);
        float v0 = fmaxf(c1[4*f+0] + b.x + sq0 * w.x, 0.0f);
        float v1 = fmaxf(c1[4*f+1] + b.y + sq0 * w.y, 0.0f);
        float v2 = fmaxf(c1[4*f+2] + b.x + sq1 * w.x, 0.0f);
        float v3 = fmaxf(c1[4*f+3] + b.y + sq1 * w.y, 0.0f);

        uint32_t h01 = packbf2(v0, v1);
        uint32_t l01 = packbf2(v0 - __uint_as_float(h01 << 16),
                               v1 - __uint_as_float(h01 & 0xFFFF0000u));
        uint32_t h23 = packbf2(v2, v3);
        uint32_t l23 = packbf2(v2 - __uint_as_float(h23 << 16),
                               v3 - __uint_as_float(h23 & 0xFFFF0000u));

        uint32_t abuf = (col >> 6) ? SO_A1 : SO_A0;
        int kc = col & 63;
        uint32_t off = hrow0 + (uint32_t)((((kc >> 3) ^ hrx) << 4) | ((kc & 7) << 1));
        *(uint32_t*)(sm + abuf + off)                 = h01;
        *(uint32_t*)(sm + abuf + 32768 + off)         = l01;
        *(uint32_t*)(sm + abuf + off + 1024)          = h23;   // +8 rows = +8*128
        *(uint32_t*)(sm + abuf + 32768 + off + 1024)  = l23;
    }
    __syncwarp();          // A rows are warp-private; warp-level visibility suffices

    // ================= GEMM2: hidden @ We2 ==================================
    float c2[64];
    #pragma unroll
    for (int i = 0; i < 64; ++i) c2[i] = 0.0f;

    mb_wait(mb0, ph0); ph0 ^= 1;
    doChunk(SO_A0, SO_B0, c2);
    mb_wait(mb1, ph1); ph1 ^= 1;
    doChunk(SO_A1, SO_B1, c2);

    // ============ epilogue2: bias, scalar head, register-direct scatter =====
    const int dst0 = sDst[r0];
    const int dst1 = sDst[r0 + 8];
    float w0 = 0.0f, w1 = 0.0f;
    #pragma unroll
    for (int f = 0; f < 16; ++f) {
        int col = 8 * f + 2 * q;
        float2 b  = *(float2*)(sBe2 + col);
        float2 wx = *(float2*)(sWx + col);
        float v0 = c2[4*f+0] + b.x;
        float v1 = c2[4*f+1] + b.y;
        float v2 = c2[4*f+2] + b.x;
        float v3 = c2[4*f+3] + b.y;
        w0 = fmaf(v0, wx.x, fmaf(v1, wx.y, w0));
        w1 = fmaf(v2, wx.x, fmaf(v3, wx.y, w1));
        if (dst0 >= 0) red2(g_mi + (size_t)dst0 * 128 + col, v0, v1);
        if (dst1 >= 0) red2(g_mi + (size_t)dst1 * 128 + col, v2, v3);
    }
    w0 += __shfl_xor_sync(0xffffffffu, w0, 1);
    w0 += __shfl_xor_sync(0xffffffffu, w0, 2);
    w1 += __shfl_xor_sync(0xffffffffu, w1, 1);
    w1 += __shfl_xor_sync(0xffffffffu, w1, 2);
    if (q == 0) {
        sW[r0]     = w0 + bx;
        sW[r0 + 8] = w1 + bx;
    }
    __syncthreads();

    if (t < ET2) {
        int di = sDst[t];
        if (di >= 0) {
            float w = sW[t];
            float4 ds = sDS[t];
            red4(g_dx4 + (size_t)di * 4, make_float4(ds.x * w, ds.y * w, ds.z * w, 0.0f));
        }
    }
}

// ---------------- node kernel (round-1 FFMA, proven) ------------------------
__global__ __launch_bounds__(NTHREADS, 2)
void node_kernel(const float* __restrict__ node,
                 const float* __restrict__ Wh1,
                 const float* __restrict__ bh1,
                 const float* __restrict__ Wh2,
                 const float* __restrict__ bh2,
                 float* __restrict__ outH,
                 int N)
{
    extern __shared__ float s[];
    float* sAH = s;
    float* sB  = s + 256 * SA;

    const int t  = threadIdx.x;
    const int r0 = blockIdx.x * TILE;

    {
        int n   = t & 63;
        int c   = t >> 6;
        int row = r0 + n;
        if (row < N) {
            const float* srow = (c < 2) ? (node + (size_t)row * Fdim + c * 64)
                                        : (g_mi + (size_t)row * 128 + (c - 2) * 64);
            int kb = c * 64;
            #pragma unroll
            for (int r = 0; r < 16; ++r) {
                float4 v = *(const float4*)(srow + r * 4);
                int k = kb + r * 4;
                sAH[(k + 0) * SA + n] = v.x;
                sAH[(k + 1) * SA + n] = v.y;
                sAH[(k + 2) * SA + n] = v.z;
                sAH[(k + 3) * SA + n] = v.w;
            }
        }
    }
    __syncthreads();

    const int m = t & 15;
    const int g = t >> 4;

    float acc[4][8];
    {
        float4 b0 = *(const float4*)(bh1 + g * 8);
        float4 b1 = *(const float4*)(bh1 + g * 8 + 4);
        #pragma unroll
        for (int i = 0; i < 4; ++i) {
            acc[i][0] = b0.x; acc[i][1] = b0.y; acc[i][2] = b0.z; acc[i][3] = b0.w;
            acc[i][4] = b1.x; acc[i][5] = b1.y; acc[i][6] = b1.z; acc[i][7] = b1.w;
        }
    }

    for (int kk = 0; kk < 256; kk += 16) {
        {
            int idx = t * 8;
            int r   = idx >> 7;
            int cc  = idx & 127;
            const float* src = Wh1 + (size_t)(kk + r) * 128 + cc;
            *(float4*)(sB + idx)     = *(const float4*)src;
            *(float4*)(sB + idx + 4) = *(const float4*)(src + 4);
        }
        __syncthreads();
        #pragma unroll
        for (int k = 0; k < 16; ++k) {
            float4 a  = *(const float4*)(sAH + (kk + k) * SA + m * 4);
            float4 w0 = *(const float4*)(sB + k * 128 + g * 8);
            float4 w1 = *(const float4*)(sB + k * 128 + g * 8 + 4);
            float av[4] = {a.x, a.y, a.z, a.w};
            float wv[8] = {w0.x, w0.y, w0.z, w0.w, w1.x, w1.y, w1.z, w1.w};
            #pragma unroll
            for (int i = 0; i < 4; ++i)
                #pragma unroll
                for (int j = 0; j < 8; ++j)
                    acc[i][j] = fmaf(av[i], wv[j], acc[i][j]);
        }
        __syncthreads();
    }

    #pragma unroll
    for (int j = 0; j < 8; ++j) {
        int h = g * 8 + j;
        float4 v;
        v.x = fmaxf(acc[0][j], 0.0f);
        v.y = fmaxf(acc[1][j], 0.0f);
        v.z = fmaxf(acc[2][j], 0.0f);
        v.w = fmaxf(acc[3][j], 0.0f);
        *(float4*)(sAH + h * SA + m * 4) = v;
    }
    __syncthreads();

    float acc2[4][8];
    {
        float4 b0 = *(const float4*)(bh2 + g * 8);
        float4 b1 = *(const float4*)(bh2 + g * 8 + 4);
        #pragma unroll
        for (int i = 0; i < 4; ++i) {
            acc2[i][0] = b0.x; acc2[i][1] = b0.y; acc2[i][2] = b0.z; acc2[i][3] = b0.w;
            acc2[i][4] = b1.x; acc2[i][5] = b1.y; acc2[i][6] = b1.z; acc2[i][7] = b1.w;
        }
    }

    for (int kk = 0; kk < 128; kk += 16) {
        {
            int idx = t * 8;
            int r   = idx >> 7;
            int cc  = idx & 127;
            const float* src = Wh2 + (size_t)(kk + r) * Fdim + cc;
            *(float4*)(sB + idx)     = *(const float4*)src;
            *(float4*)(sB + idx + 4) = *(const float4*)(src + 4);
        }
        __syncthreads();
        #pragma unroll
        for (int k = 0; k < 16; ++k) {
            float4 a  = *(const float4*)(sAH + (kk + k) * SA + m * 4);
            float4 w0 = *(const float4*)(sB + k * 128 + g * 8);
            float4 w1 = *(const float4*)(sB + k * 128 + g * 8 + 4);
            float av[4] = {a.x, a.y, a.z, a.w};
            float wv[8] = {w0.x, w0.y, w0.z, w0.w, w1.x, w1.y, w1.z, w1.w};
            #pragma unroll
            for (int i = 0; i < 4; ++i)
                #pragma unroll
                for (int j = 0; j < 8; ++j)
                    acc2[i][j] = fmaf(av[i], wv[j], acc2[i][j]);
        }
        __syncthreads();
    }

    #pragma unroll
    for (int i = 0; i < 4; ++i) {
        int row = r0 + m * 4 + i;
        if (row < N) {
            float4 v0, v1;
            v0.x = acc2[i][0]; v0.y = acc2[i][1]; v0.z = acc2[i][2]; v0.w = acc2[i][3];
            v1.x = acc2[i][4]; v1.y = acc2[i][5]; v1.z = acc2[i][6]; v1.w = acc2[i][7];
            *(float4*)(outH + (size_t)row * Fdim + g * 8)     = v0;
            *(float4*)(outH + (size_t)row * Fdim + g * 8 + 4) = v1;
        }
    }
}

// ---------------- coordinate update -----------------------------------------
__global__ void x_kernel(const float* __restrict__ coord,
                         float* __restrict__ outX,
                         int n3, float C)
{
    int i = blockIdx.x * blockDim.x + threadIdx.x;
    if (i < n3) {
        int n = i / 3, d = i - n * 3;
        outX[i] = coord[i] + g_dx4[(size_t)n * 4 + d] * C;
    }
}

// ---------------- launch -----------------------------------------------------
extern "C" void kernel_launch(void* const* d_in, const int* in_sizes, int n_in,
                              void* d_out, int out_size)
{
    const float* node  = (const float*)d_in[0];
    const float* coord = (const float*)d_in[1];
    const int*   ei    = (const int*)d_in[2];
    const float* We1   = (const float*)d_in[3];
    const float* be1   = (const float*)d_in[4];
    const float* We2   = (const float*)d_in[5];
    const float* be2   = (const float*)d_in[6];
    const float* Wx    = (const float*)d_in[7];
    const float* bx    = (const float*)d_in[8];
    const float* Wh1   = (const float*)d_in[9];
    const float* bh1   = (const float*)d_in[10];
    const float* Wh2   = (const float*)d_in[11];
    const float* bh2   = (const float*)d_in[12];

    const int N = in_sizes[0] / Fdim;
    const int E = in_sizes[2] / 2;

    float* outH = (float*)d_out;
    float* outX = outH + (size_t)N * Fdim;

    const int node_smem = (256 * SA + 16 * 128) * 4;
    cudaFuncSetAttribute(edge_kernel, cudaFuncAttributeMaxDynamicSharedMemorySize, EDGE_SMEM);
    cudaFuncSetAttribute(node_kernel, cudaFuncAttributeMaxDynamicSharedMemorySize, node_smem);

    prep_kernel<<<(49152 + 255) / 256, 256>>>(We1, We2);
    {
        int n_mi = N * 128;
        zero_kernel<<<(n_mi + 255) / 256, 256>>>(n_mi, N * 4);
    }
    {
        int grid = (E + ET2 - 1) / ET2;
        edge_kernel<<<grid, 512, EDGE_SMEM>>>(node, coord, ei, We1, be1, be2, Wx, bx, E);
    }
    {
        int grid = (N + TILE - 1) / TILE;
        node_kernel<<<grid, NTHREADS, node_smem>>>(node, Wh1, bh1, Wh2, bh2, outH, N);
    }
    {
        int n3 = N * 3;
        float C = 1.0f / (float)(N - 1);
        x_kernel<<<(n3 + 255) / 256, 256>>>(coord, outX, n3, C);
    }
}

// round 6
// speedup vs baseline: 2.7494x; 1.2100x over previous
#include <cuda_runtime.h>
#include <cuda_fp16.h>
#include <cstdint>

#define Fdim 128
#define ET2  256              // edges per CTA tile (MMA M)
#define MAXN 50000
#define TILE 64               // node-kernel row tile
#define NTHREADS 256
#define SA 72                 // node-kernel fp32 padded stride

// ---------------- scratch (static device arrays; allocation-free) ----------
__device__ float g_mi[(size_t)MAXN * 128];
__device__ float g_dx4[(size_t)MAXN * 4];
// pre-split swizzled weight chunk images: [hi 8192 | lo 8192] fp16, rows=n(128), kc(64)
__device__ __align__(16) __half gB1[4][16384];
__device__ __align__(16) __half gB2[2][16384];

#define BCH 32768            /* bytes per B chunk (hi+lo) */

// ---------------- PTX helpers ----------------------------------------------
__device__ __forceinline__ uint32_t smem_u32(const void* p) {
    uint32_t a;
    asm("{ .reg .u64 t; cvta.to.shared.u64 t, %1; cvt.u32.u64 %0, t; }" : "=r"(a) : "l"(p));
    return a;
}

#define LDSM4(r0, r1, r2, r3, addr) \
    asm volatile("ldmatrix.sync.aligned.m8n8.x4.shared.b16 {%0,%1,%2,%3}, [%4];" \
                 : "=r"(r0), "=r"(r1), "=r"(r2), "=r"(r3) : "r"(addr))

#define MMA16816(cp, a0, a1, a2, a3, b0, b1) \
    asm volatile("mma.sync.aligned.m16n8k16.row.col.f32.f16.f16.f32 " \
                 "{%0,%1,%2,%3},{%4,%5,%6,%7},{%8,%9},{%0,%1,%2,%3};" \
                 : "+f"((cp)[0]), "+f"((cp)[1]), "+f"((cp)[2]), "+f"((cp)[3]) \
                 : "r"(a0), "r"(a1), "r"(a2), "r"(a3), "r"(b0), "r"(b1))

#define MB_INIT(mb, c) asm volatile("mbarrier.init.shared.b64 [%0], %1;" :: "r"(mb), "r"(c) : "memory")
#define MB_EXPECT(mb, b) asm volatile("mbarrier.arrive.expect_tx.shared.b64 _, [%0], %1;" :: "r"(mb), "r"(b) : "memory")
#define BULK_G2S(dst, src, bytes, mb) \
    asm volatile("cp.async.bulk.shared::cluster.global.mbarrier::complete_tx::bytes [%0], [%1], %2, [%3];" \
                 :: "r"(dst), "l"(src), "r"(bytes), "r"(mb) : "memory")

__device__ __forceinline__ void mb_wait(uint32_t mb, uint32_t parity) {
    uint32_t done;
    asm volatile("{ .reg .pred p; mbarrier.try_wait.parity.acquire.cta.shared::cta.b64 p, [%1], %2; selp.b32 %0, 1, 0, p; }"
                 : "=r"(done) : "r"(mb), "r"(parity) : "memory");
    if (!done) {
        asm volatile("{ .reg .pred P1;\nW%=:\n mbarrier.try_wait.parity.acquire.cta.shared::cta.b64 P1, [%0], %1, 0x989680;\n @P1 bra.uni D%=;\n bra.uni W%=;\nD%=:\n}"
                     :: "r"(mb), "r"(parity) : "memory");
    }
}

__device__ __forceinline__ void red2(float* p, float x, float y) {
    asm volatile("red.global.add.v2.f32 [%0], {%1,%2};" :: "l"(p), "f"(x), "f"(y) : "memory");
}
__device__ __forceinline__ void red4(float* p, float4 v) {
    asm volatile("red.global.add.v4.f32 [%0], {%1,%2,%3,%4};"
                 :: "l"(p), "f"(v.x), "f"(v.y), "f"(v.z), "f"(v.w) : "memory");
}

// pack two floats -> fp16x2 (lower = a, upper = b)
__device__ __forceinline__ uint32_t packhf2(float a, float b) {
    uint32_t r;
    asm("cvt.rn.f16x2.f32 %0, %1, %2;" : "=r"(r) : "f"(b), "f"(a));
    return r;
}

// swizzled element offset within a [row][kc] tile, 64 fp16 per row (128 B)
__host__ __device__ __forceinline__ int swoff(int n, int kc) {
    return n * 64 + ((((kc >> 3) ^ (n & 7)) << 3) | (kc & 7));
}

// ---------------- prep: split weights into swizzled fp16 chunk images -------
__global__ void prep_kernel(const float* __restrict__ We1, const float* __restrict__ We2)
{
    int id = blockIdx.x * blockDim.x + threadIdx.x;
    if (id < 32768) {                       // B1: 4 chunks x 128 n x 64 kc
        int c   = id >> 13;
        int rem = id & 8191;
        int n   = rem >> 6;
        int kc  = rem & 63;
        float v = We1[(size_t)(c * 64 + kc) * 128 + n];
        __half hi = __float2half_rn(v);
        float lo = v - __half2float(hi);
        int o = swoff(n, kc);
        gB1[c][o]        = hi;
        gB1[c][8192 + o] = __float2half_rn(lo);
    } else if (id < 49152) {                // B2: 2 chunks
        int id2 = id - 32768;
        int c   = id2 >> 13;
        int rem = id2 & 8191;
        int n   = rem >> 6;
        int kc  = rem & 63;
        float v = We2[(size_t)(c * 64 + kc) * 128 + n];
        __half hi = __float2half_rn(v);
        float lo = v - __half2float(hi);
        int o = swoff(n, kc);
        gB2[c][o]        = hi;
        gB2[c][8192 + o] = __float2half_rn(lo);
    }
}

// ---------------- zero scratch ----------------------------------------------
__global__ void zero_kernel(int n_mi, int n_dx)
{
    int i = blockIdx.x * blockDim.x + threadIdx.x;
    if (i < n_mi) g_mi[i] = 0.0f;
    if (i < n_dx) g_dx4[i] = 0.0f;
}

// ---------------- edge kernel ------------------------------------------------
// SMEM layout (bytes): A buffers hold 256 rows x 64 kc fp16 (32K each)
#define SO_A0   0
#define SO_A1   32768
#define SO_B0   65536      /* hi 16K | lo 16K */
#define SO_B1   98304
#define SO_DS   131072     /* float4[256] */
#define SO_W    135168     /* float[256] */
#define SO_DST  136192     /* int[256] */
#define SO_WX   137216
#define SO_BE1  137728
#define SO_BE2  138240
#define SO_W256 138752
#define SO_MB   139264
#define EDGE_SMEM 139296

__global__ __launch_bounds__(512, 1)
void edge_kernel(const float* __restrict__ node,
                 const float* __restrict__ coord,
                 const int*   __restrict__ ei,
                 const float* __restrict__ We1,
                 const float* __restrict__ be1,
                 const float* __restrict__ be2,
                 const float* __restrict__ Wx,
                 const float* __restrict__ bxp,
                 int E)
{
    extern __shared__ char sm[];
    const uint32_t sbase = smem_u32(sm);

    float4* sDS  = (float4*)(sm + SO_DS);
    float*  sW   = (float*)(sm + SO_W);
    int*    sDst = (int*)(sm + SO_DST);
    float*  sWx  = (float*)(sm + SO_WX);
    float*  sBe1 = (float*)(sm + SO_BE1);
    float*  sBe2 = (float*)(sm + SO_BE2);
    float*  sW256= (float*)(sm + SO_W256);

    const int t    = threadIdx.x;
    const int wid  = t >> 5;
    const int lane = t & 31;
    const int e0   = blockIdx.x * ET2;
    const float bx = bxp[0];

    const uint32_t mb0 = sbase + SO_MB;
    const uint32_t mb1 = sbase + SO_MB + 8;

    if (t == 0) { MB_INIT(mb0, 1); MB_INIT(mb1, 1); }

    // ---- per-edge metadata ----
    if (t < ET2) {
        int eg = e0 + t;
        float dx = 0.f, dy = 0.f, dz = 0.f;
        int di = -1;
        if (eg < E) {
            int si = ei[eg];
            di     = ei[E + eg];
            dx = coord[(size_t)di * 3 + 0] - coord[(size_t)si * 3 + 0];
            dy = coord[(size_t)di * 3 + 1] - coord[(size_t)si * 3 + 1];
            dz = coord[(size_t)di * 3 + 2] - coord[(size_t)si * 3 + 2];
        }
        sDS[t]  = make_float4(dx, dy, dz, dx * dx + dy * dy + dz * dz);
        sDst[t] = di;
    }
    if (t < 128) {
        sWx[t]  = Wx[t];
        sBe1[t] = be1[t];
        sBe2[t] = be2[t];
        sW256[t]= We1[(size_t)256 * 128 + t];
    }
    __syncthreads();

    // launch first two B chunk copies
    if (t == 0) {
        MB_EXPECT(mb0, BCH);
        BULK_G2S(sbase + SO_B0, (const void*)gB1[0], BCH, mb0);
        MB_EXPECT(mb1, BCH);
        BULK_G2S(sbase + SO_B1, (const void*)gB1[1], BCH, mb1);
    }

    // gather role: 2 threads per edge row
    const int grow  = t >> 1;          // 0..255
    const int ghalf = t & 1;           // which 32-col half
    int gsi = 0, gdi = 0;
    const bool gvalid = (e0 + grow) < E;
    if (gvalid) { gsi = ei[e0 + grow]; gdi = ei[E + e0 + grow]; }
    const uint32_t g_rowoff = (uint32_t)grow * 128;
    const int      g_rx     = grow & 7;

    // stage A chunk c (gather + fp16 convert + swizzled STS)
    auto stageA = [&](int c, uint32_t abo) {
        const float* rp = node + (size_t)(c < 2 ? gdi : gsi) * 128 + (c & 1) * 64 + ghalf * 32;
        #pragma unroll
        for (int u = 0; u < 4; ++u) {
            uint4 H;
            if (gvalid) {
                float4 v0 = *(const float4*)(rp + u * 8);
                float4 v1 = *(const float4*)(rp + u * 8 + 4);
                H.x = packhf2(v0.x, v0.y);
                H.y = packhf2(v0.z, v0.w);
                H.z = packhf2(v1.x, v1.y);
                H.w = packhf2(v1.z, v1.w);
            } else {
                H = make_uint4(0u, 0u, 0u, 0u);
            }
            uint32_t off = g_rowoff + (uint32_t)(((ghalf * 4 + u) ^ g_rx) << 4);
            *(uint4*)(sm + abo + off) = H;
        }
    };

    // ldmatrix per-thread addressing constants
    const int seg = lane >> 3;
    const int lnx = lane & 7;
    const int sA_r = seg & 1;          // A: +8 rows
    const int sA_g = (seg >> 1) & 1;   // A: +16B group
    const int sB_r = (seg >> 1) & 1;   // B: +8 rows
    const int sB_g = seg & 1;          // B: +16B group
    const uint32_t a_rowoff = (uint32_t)(wid * 16 + lnx + sA_r * 8) * 128;
    const uint32_t b_rowoff = (uint32_t)(lnx + sB_r * 8) * 128;

    // MMA over one 64-k chunk: A single fp16 at Ab, B hi at Bb, lo at Bb+16384
    auto doChunk = [&](uint32_t Ab, uint32_t Bb, float* cc) {
        #pragma unroll
        for (int ks = 0; ks < 4; ++ks) {
            uint32_t ag = (uint32_t)(((2 * ks) | sA_g) ^ lnx) << 4;
            uint32_t bg = (uint32_t)(((2 * ks) | sB_g) ^ lnx) << 4;
            uint32_t a0,a1,a2,a3;
            LDSM4(a0,a1,a2,a3, sbase + Ab + a_rowoff + ag);
            #pragma unroll
            for (int jb = 0; jb < 8; ++jb) {
                uint32_t baddr = sbase + Bb + b_rowoff + (uint32_t)(jb * 2048) + bg;
                uint32_t bh0,bh1,bh2,bh3, bl0,bl1,bl2,bl3;
                LDSM4(bh0,bh1,bh2,bh3, baddr);
                LDSM4(bl0,bl1,bl2,bl3, baddr + 16384);
                float* cp0 = cc + 8 * jb;
                float* cp1 = cc + 8 * jb + 4;
                MMA16816(cp0, a0,a1,a2,a3, bh0,bh1);
                MMA16816(cp1, a0,a1,a2,a3, bh2,bh3);
                MMA16816(cp0, a0,a1,a2,a3, bl0,bl1);
                MMA16816(cp1, a0,a1,a2,a3, bl2,bl3);
            }
        }
    };

    float c1[64];
    #pragma unroll
    for (int i = 0; i < 64; ++i) c1[i] = 0.0f;

    stageA(0, SO_A0);
    __syncthreads();

    uint32_t ph0 = 0, ph1 = 0;

    // ================= GEMM1: 4 k-chunks of 64 ==============================
    #pragma unroll 1
    for (int c = 0; c < 4; ++c) {
        if (c & 1) { mb_wait(mb1, ph1); ph1 ^= 1; }
        else       { mb_wait(mb0, ph0); ph0 ^= 1; }

        if (c < 3) stageA(c + 1, (c & 1) ? SO_A0 : SO_A1);   // writes other A buf

        doChunk((c & 1) ? SO_A1 : SO_A0, (c & 1) ? SO_B1 : SO_B0, c1);
        __syncthreads();

        if (t == 0) {      // refill just-freed B buf with chunk c+2
            const void* nsrc = (c == 0) ? (const void*)gB1[2]
                             : (c == 1) ? (const void*)gB1[3]
                             : (c == 2) ? (const void*)gB2[0]
                                        : (const void*)gB2[1];
            uint32_t dst = (c & 1) ? (sbase + SO_B1) : (sbase + SO_B0);
            uint32_t mb  = (c & 1) ? mb1 : mb0;
            MB_EXPECT(mb, BCH);
            BULK_G2S(dst, nsrc, BCH, mb);
        }
    }

    // ============ epilogue1: relu + rank-1 sqdist + bias -> fp16 to A bufs ===
    const int r0 = wid * 16 + (lane >> 2);
    const int q  = lane & 3;
    const float sq0 = sDS[r0].w;
    const float sq1 = sDS[r0 + 8].w;
    const uint32_t hrow0 = (uint32_t)r0 * 128;
    const int      hrx   = r0 & 7;          // (r0+8)&7 == r0&7
    #pragma unroll
    for (int f = 0; f < 16; ++f) {
        int col = 8 * f + 2 * q;
        float2 b = *(float2*)(sBe1 + col);
        float2 w = *(float2*)(sW256 + col);
        float v0 = fmaxf(c1[4*f+0] + b.x + sq0 * w.x, 0.0f);
        float v1 = fmaxf(c1[4*f+1] + b.y + sq0 * w.y, 0.0f);
        float v2 = fmaxf(c1[4*f+2] + b.x + sq1 * w.x, 0.0f);
        float v3 = fmaxf(c1[4*f+3] + b.y + sq1 * w.y, 0.0f);

        uint32_t h01 = packhf2(v0, v1);
        uint32_t h23 = packhf2(v2, v3);

        uint32_t abuf = (col >> 6) ? SO_A1 : SO_A0;
        int kc = col & 63;
        uint32_t off = hrow0 + (uint32_t)((((kc >> 3) ^ hrx) << 4) | ((kc & 7) << 1));
        *(uint32_t*)(sm + abuf + off)        = h01;
        *(uint32_t*)(sm + abuf + off + 1024) = h23;   // +8 rows = +8*128 B
    }
    __syncwarp();          // A rows are warp-private; warp-level visibility suffices

    // ================= GEMM2: hidden @ We2 ==================================
    float c2[64];
    #pragma unroll
    for (int i = 0; i < 64; ++i) c2[i] = 0.0f;

    mb_wait(mb0, ph0); ph0 ^= 1;
    doChunk(SO_A0, SO_B0, c2);
    mb_wait(mb1, ph1); ph1 ^= 1;
    doChunk(SO_A1, SO_B1, c2);

    // ============ epilogue2: bias, scalar head, register-direct scatter =====
    const int dst0 = sDst[r0];
    const int dst1 = sDst[r0 + 8];
    float w0 = 0.0f, w1 = 0.0f;
    #pragma unroll
    for (int f = 0; f < 16; ++f) {
        int col = 8 * f + 2 * q;
        float2 b  = *(float2*)(sBe2 + col);
        float2 wx = *(float2*)(sWx + col);
        float v0 = c2[4*f+0] + b.x;
        float v1 = c2[4*f+1] + b.y;
        float v2 = c2[4*f+2] + b.x;
        float v3 = c2[4*f+3] + b.y;
        w0 = fmaf(v0, wx.x, fmaf(v1, wx.y, w0));
        w1 = fmaf(v2, wx.x, fmaf(v3, wx.y, w1));
        if (dst0 >= 0) red2(g_mi + (size_t)dst0 * 128 + col, v0, v1);
        if (dst1 >= 0) red2(g_mi + (size_t)dst1 * 128 + col, v2, v3);
    }
    w0 += __shfl_xor_sync(0xffffffffu, w0, 1);
    w0 += __shfl_xor_sync(0xffffffffu, w0, 2);
    w1 += __shfl_xor_sync(0xffffffffu, w1, 1);
    w1 += __shfl_xor_sync(0xffffffffu, w1, 2);
    if (q == 0) {
        sW[r0]     = w0 + bx;
        sW[r0 + 8] = w1 + bx;
    }
    __syncthreads();

    if (t < ET2) {
        int di = sDst[t];
        if (di >= 0) {
            float w = sW[t];
            float4 ds = sDS[t];
            red4(g_dx4 + (size_t)di * 4, make_float4(ds.x * w, ds.y * w, ds.z * w, 0.0f));
        }
    }
}

// ---------------- node kernel (round-1 FFMA, proven) ------------------------
__global__ __launch_bounds__(NTHREADS, 2)
void node_kernel(const float* __restrict__ node,
                 const float* __restrict__ Wh1,
                 const float* __restrict__ bh1,
                 const float* __restrict__ Wh2,
                 const float* __restrict__ bh2,
                 float* __restrict__ outH,
                 int N)
{
    extern __shared__ float s[];
    float* sAH = s;
    float* sB  = s + 256 * SA;

    const int t  = threadIdx.x;
    const int r0 = blockIdx.x * TILE;

    {
        int n   = t & 63;
        int c   = t >> 6;
        int row = r0 + n;
        if (row < N) {
            const float* srow = (c < 2) ? (node + (size_t)row * Fdim + c * 64)
                                        : (g_mi + (size_t)row * 128 + (c - 2) * 64);
            int kb = c * 64;
            #pragma unroll
            for (int r = 0; r < 16; ++r) {
                float4 v = *(const float4*)(srow + r * 4);
                int k = kb + r * 4;
                sAH[(k + 0) * SA + n] = v.x;
                sAH[(k + 1) * SA + n] = v.y;
                sAH[(k + 2) * SA + n] = v.z;
                sAH[(k + 3) * SA + n] = v.w;
            }
        }
    }
    __syncthreads();

    const int m = t & 15;
    const int g = t >> 4;

    float acc[4][8];
    {
        float4 b0 = *(const float4*)(bh1 + g * 8);
        float4 b1 = *(const float4*)(bh1 + g * 8 + 4);
        #pragma unroll
        for (int i = 0; i < 4; ++i) {
            acc[i][0] = b0.x; acc[i][1] = b0.y; acc[i][2] = b0.z; acc[i][3] = b0.w;
            acc[i][4] = b1.x; acc[i][5] = b1.y; acc[i][6] = b1.z; acc[i][7] = b1.w;
        }
    }

    for (int kk = 0; kk < 256; kk += 16) {
        {
            int idx = t * 8;
            int r   = idx >> 7;
            int cc  = idx & 127;
            const float* src = Wh1 + (size_t)(kk + r) * 128 + cc;
            *(float4*)(sB + idx)     = *(const float4*)src;
            *(float4*)(sB + idx + 4) = *(const float4*)(src + 4);
        }
        __syncthreads();
        #pragma unroll
        for (int k = 0; k < 16; ++k) {
            float4 a  = *(const float4*)(sAH + (kk + k) * SA + m * 4);
            float4 w0 = *(const float4*)(sB + k * 128 + g * 8);
            float4 w1 = *(const float4*)(sB + k * 128 + g * 8 + 4);
            float av[4] = {a.x, a.y, a.z, a.w};
            float wv[8] = {w0.x, w0.y, w0.z, w0.w, w1.x, w1.y, w1.z, w1.w};
            #pragma unroll
            for (int i = 0; i < 4; ++i)
                #pragma unroll
                for (int j = 0; j < 8; ++j)
                    acc[i][j] = fmaf(av[i], wv[j], acc[i][j]);
        }
        __syncthreads();
    }

    #pragma unroll
    for (int j = 0; j < 8; ++j) {
        int h = g * 8 + j;
        float4 v;
        v.x = fmaxf(acc[0][j], 0.0f);
        v.y = fmaxf(acc[1][j], 0.0f);
        v.z = fmaxf(acc[2][j], 0.0f);
        v.w = fmaxf(acc[3][j], 0.0f);
        *(float4*)(sAH + h * SA + m * 4) = v;
    }
    __syncthreads();

    float acc2[4][8];
    {
        float4 b0 = *(const float4*)(bh2 + g * 8);
        float4 b1 = *(const float4*)(bh2 + g * 8 + 4);
        #pragma unroll
        for (int i = 0; i < 4; ++i) {
            acc2[i][0] = b0.x; acc2[i][1] = b0.y; acc2[i][2] = b0.z; acc2[i][3] = b0.w;
            acc2[i][4] = b1.x; acc2[i][5] = b1.y; acc2[i][6] = b1.z; acc2[i][7] = b1.w;
        }
    }

    for (int kk = 0; kk < 128; kk += 16) {
        {
            int idx = t * 8;
            int r   = idx >> 7;
            int cc  = idx & 127;
            const float* src = Wh2 + (size_t)(kk + r) * Fdim + cc;
            *(float4*)(sB + idx)     = *(const float4*)src;
            *(float4*)(sB + idx + 4) = *(const float4*)(src + 4);
        }
        __syncthreads();
        #pragma unroll
        for (int k = 0; k < 16; ++k) {
            float4 a  = *(const float4*)(sAH + (kk + k) * SA + m * 4);
            float4 w0 = *(const float4*)(sB + k * 128 + g * 8);
            float4 w1 = *(const float4*)(sB + k * 128 + g * 8 + 4);
            float av[4] = {a.x, a.y, a.z, a.w};
            float wv[8] = {w0.x, w0.y, w0.z, w0.w, w1.x, w1.y, w1.z, w1.w};
            #pragma unroll
            for (int i = 0; i < 4; ++i)
                #pragma unroll
                for (int j = 0; j < 8; ++j)
                    acc2[i][j] = fmaf(av[i], wv[j], acc2[i][j]);
        }
        __syncthreads();
    }

    #pragma unroll
    for (int i = 0; i < 4; ++i) {
        int row = r0 + m * 4 + i;
        if (row < N) {
            float4 v0, v1;
            v0.x = acc2[i][0]; v0.y = acc2[i][1]; v0.z = acc2[i][2]; v0.w = acc2[i][3];
            v1.x = acc2[i][4]; v1.y = acc2[i][5]; v1.z = acc2[i][6]; v1.w = acc2[i][7];
            *(float4*)(outH + (size_t)row * Fdim + g * 8)     = v0;
            *(float4*)(outH + (size_t)row * Fdim + g * 8 + 4) = v1;
        }
    }
}

// ---------------- coordinate update -----------------------------------------
__global__ void x_kernel(const float* __restrict__ coord,
                         float* __restrict__ outX,
                         int n3, float C)
{
    int i = blockIdx.x * blockDim.x + threadIdx.x;
    if (i < n3) {
        int n = i / 3, d = i - n * 3;
        outX[i] = coord[i] + g_dx4[(size_t)n * 4 + d] * C;
    }
}

// ---------------- launch -----------------------------------------------------
extern "C" void kernel_launch(void* const* d_in, const int* in_sizes, int n_in,
                              void* d_out, int out_size)
{
    const float* node  = (const float*)d_in[0];
    const float* coord = (const float*)d_in[1];
    const int*   ei    = (const int*)d_in[2];
    const float* We1   = (const float*)d_in[3];
    const float* be1   = (const float*)d_in[4];
    const float* We2   = (const float*)d_in[5];
    const float* be2   = (const float*)d_in[6];
    const float* Wx    = (const float*)d_in[7];
    const float* bx    = (const float*)d_in[8];
    const float* Wh1   = (const float*)d_in[9];
    const float* bh1   = (const float*)d_in[10];
    const float* Wh2   = (const float*)d_in[11];
    const float* bh2   = (const float*)d_in[12];

    const int N = in_sizes[0] / Fdim;
    const int E = in_sizes[2] / 2;

    float* outH = (float*)d_out;
    float* outX = outH + (size_t)N * Fdim;

    const int node_smem = (256 * SA + 16 * 128) * 4;
    cudaFuncSetAttribute(edge_kernel, cudaFuncAttributeMaxDynamicSharedMemorySize, EDGE_SMEM);
    cudaFuncSetAttribute(node_kernel, cudaFuncAttributeMaxDynamicSharedMemorySize, node_smem);

    prep_kernel<<<(49152 + 255) / 256, 256>>>(We1, We2);
    {
        int n_mi = N * 128;
        zero_kernel<<<(n_mi + 255) / 256, 256>>>(n_mi, N * 4);
    }
    {
        int grid = (E + ET2 - 1) / ET2;
        edge_kernel<<<grid, 512, EDGE_SMEM>>>(node, coord, ei, We1, be1, be2, Wx, bx, E);
    }
    {
        int grid = (N + TILE - 1) / TILE;
        node_kernel<<<grid, NTHREADS, node_smem>>>(node, Wh1, bh1, Wh2, bh2, outH, N);
    }
    {
        int n3 = N * 3;
        float C = 1.0f / (float)(N - 1);
        x_kernel<<<(n3 + 255) / 256, 256>>>(coord, outX, n3, C);
    }
}

// round 7
// speedup vs baseline: 3.3317x; 1.2118x over previous
#include <cuda_runtime.h>
#include <cuda_fp16.h>
#include <cstdint>

#define Fdim 128
#define ET2  256              // edges per CTA tile (MMA M)
#define MAXN 50000
#define TILE 64               // node-kernel row tile
#define NTHREADS 256
#define SA 72                 // node-kernel fp32 padded stride

// ---------------- scratch (static device arrays; allocation-free) ----------
__device__ float g_mi[(size_t)MAXN * 128];
__device__ float g_dx4[(size_t)MAXN * 4];
// swizzled fp16 weight chunk images: rows=n(128), kc(64)
__device__ __align__(16) __half gB1[4][8192];
__device__ __align__(16) __half gB2[2][8192];

#define BCH 16384            /* bytes per B chunk */

// ---------------- PTX helpers ----------------------------------------------
__device__ __forceinline__ uint32_t smem_u32(const void* p) {
    uint32_t a;
    asm("{ .reg .u64 t; cvta.to.shared.u64 t, %1; cvt.u32.u64 %0, t; }" : "=r"(a) : "l"(p));
    return a;
}

#define LDSM4(r0, r1, r2, r3, addr) \
    asm volatile("ldmatrix.sync.aligned.m8n8.x4.shared.b16 {%0,%1,%2,%3}, [%4];" \
                 : "=r"(r0), "=r"(r1), "=r"(r2), "=r"(r3) : "r"(addr))

#define MMA16816(cp, a0, a1, a2, a3, b0, b1) \
    asm volatile("mma.sync.aligned.m16n8k16.row.col.f32.f16.f16.f32 " \
                 "{%0,%1,%2,%3},{%4,%5,%6,%7},{%8,%9},{%0,%1,%2,%3};" \
                 : "+f"((cp)[0]), "+f"((cp)[1]), "+f"((cp)[2]), "+f"((cp)[3]) \
                 : "r"(a0), "r"(a1), "r"(a2), "r"(a3), "r"(b0), "r"(b1))

#define MB_INIT(mb, c) asm volatile("mbarrier.init.shared.b64 [%0], %1;" :: "r"(mb), "r"(c) : "memory")
#define MB_EXPECT(mb, b) asm volatile("mbarrier.arrive.expect_tx.shared.b64 _, [%0], %1;" :: "r"(mb), "r"(b) : "memory")
#define BULK_G2S(dst, src, bytes, mb) \
    asm volatile("cp.async.bulk.shared::cluster.global.mbarrier::complete_tx::bytes [%0], [%1], %2, [%3];" \
                 :: "r"(dst), "l"(src), "r"(bytes), "r"(mb) : "memory")

__device__ __forceinline__ void mb_wait(uint32_t mb, uint32_t parity) {
    uint32_t done;
    asm volatile("{ .reg .pred p; mbarrier.try_wait.parity.acquire.cta.shared::cta.b64 p, [%1], %2; selp.b32 %0, 1, 0, p; }"
                 : "=r"(done) : "r"(mb), "r"(parity) : "memory");
    if (!done) {
        asm volatile("{ .reg .pred P1;\nW%=:\n mbarrier.try_wait.parity.acquire.cta.shared::cta.b64 P1, [%0], %1, 0x989680;\n @P1 bra.uni D%=;\n bra.uni W%=;\nD%=:\n}"
                     :: "r"(mb), "r"(parity) : "memory");
    }
}

__device__ __forceinline__ void red2(float* p, float x, float y) {
    asm volatile("red.global.add.v2.f32 [%0], {%1,%2};" :: "l"(p), "f"(x), "f"(y) : "memory");
}
__device__ __forceinline__ void red4(float* p, float4 v) {
    asm volatile("red.global.add.v4.f32 [%0], {%1,%2,%3,%4};"
                 :: "l"(p), "f"(v.x), "f"(v.y), "f"(v.z), "f"(v.w) : "memory");
}

// pack two floats -> fp16x2 (lower = a, upper = b)
__device__ __forceinline__ uint32_t packhf2(float a, float b) {
    uint32_t r;
    asm("cvt.rn.f16x2.f32 %0, %1, %2;" : "=r"(r) : "f"(b), "f"(a));
    return r;
}

// swizzled element offset within a [row][kc] tile, 64 fp16 per row (128 B)
__host__ __device__ __forceinline__ int swoff(int n, int kc) {
    return n * 64 + ((((kc >> 3) ^ (n & 7)) << 3) | (kc & 7));
}

// ---------------- prep: swizzled fp16 weight chunk images -------------------
__global__ void prep_kernel(const float* __restrict__ We1, const float* __restrict__ We2)
{
    int id = blockIdx.x * blockDim.x + threadIdx.x;
    if (id < 32768) {                       // B1: 4 chunks x 128 n x 64 kc
        int c   = id >> 13;
        int rem = id & 8191;
        int n   = rem >> 6;
        int kc  = rem & 63;
        float v = We1[(size_t)(c * 64 + kc) * 128 + n];
        gB1[c][swoff(n, kc)] = __float2half_rn(v);
    } else if (id < 49152) {                // B2: 2 chunks
        int id2 = id - 32768;
        int c   = id2 >> 13;
        int rem = id2 & 8191;
        int n   = rem >> 6;
        int kc  = rem & 63;
        float v = We2[(size_t)(c * 64 + kc) * 128 + n];
        gB2[c][swoff(n, kc)] = __float2half_rn(v);
    }
}

// ---------------- zero scratch ----------------------------------------------
__global__ void zero_kernel(int n_mi, int n_dx)
{
    int i = blockIdx.x * blockDim.x + threadIdx.x;
    if (i < n_mi) g_mi[i] = 0.0f;
    if (i < n_dx) g_dx4[i] = 0.0f;
}

// ---------------- edge kernel ------------------------------------------------
// SMEM layout (bytes): A buffers 256 rows x 64 kc fp16 (32K each); B bufs 16K
#define SO_A0   0
#define SO_A1   32768
#define SO_B0   65536
#define SO_B1   81920
#define SO_DS   98304      /* float4[256] */
#define SO_W    102400     /* float[256] */
#define SO_DST  103424     /* int[256] */
#define SO_WX   104448
#define SO_BE1  104960
#define SO_BE2  105472
#define SO_W256 105984
#define SO_MB   106496
#define EDGE_SMEM 106528

__global__ __launch_bounds__(512, 1)
void edge_kernel(const float* __restrict__ node,
                 const float* __restrict__ coord,
                 const int*   __restrict__ ei,
                 const float* __restrict__ We1,
                 const float* __restrict__ be1,
                 const float* __restrict__ be2,
                 const float* __restrict__ Wx,
                 const float* __restrict__ bxp,
                 int E)
{
    extern __shared__ char sm[];
    const uint32_t sbase = smem_u32(sm);

    float4* sDS  = (float4*)(sm + SO_DS);
    float*  sW   = (float*)(sm + SO_W);
    int*    sDst = (int*)(sm + SO_DST);
    float*  sWx  = (float*)(sm + SO_WX);
    float*  sBe1 = (float*)(sm + SO_BE1);
    float*  sBe2 = (float*)(sm + SO_BE2);
    float*  sW256= (float*)(sm + SO_W256);

    const int t    = threadIdx.x;
    const int wid  = t >> 5;
    const int lane = t & 31;
    const int e0   = blockIdx.x * ET2;
    const float bx = bxp[0];

    const uint32_t mb0 = sbase + SO_MB;
    const uint32_t mb1 = sbase + SO_MB + 8;

    if (t == 0) { MB_INIT(mb0, 1); MB_INIT(mb1, 1); }

    // ---- per-edge metadata ----
    if (t < ET2) {
        int eg = e0 + t;
        float dx = 0.f, dy = 0.f, dz = 0.f;
        int di = -1;
        if (eg < E) {
            int si = ei[eg];
            di     = ei[E + eg];
            dx = coord[(size_t)di * 3 + 0] - coord[(size_t)si * 3 + 0];
            dy = coord[(size_t)di * 3 + 1] - coord[(size_t)si * 3 + 1];
            dz = coord[(size_t)di * 3 + 2] - coord[(size_t)si * 3 + 2];
        }
        sDS[t]  = make_float4(dx, dy, dz, dx * dx + dy * dy + dz * dz);
        sDst[t] = di;
    }
    if (t < 128) {
        sWx[t]  = Wx[t];
        sBe1[t] = be1[t];
        sBe2[t] = be2[t];
        sW256[t]= We1[(size_t)256 * 128 + t];
    }
    __syncthreads();

    // launch first two B chunk copies
    if (t == 0) {
        MB_EXPECT(mb0, BCH);
        BULK_G2S(sbase + SO_B0, (const void*)gB1[0], BCH, mb0);
        MB_EXPECT(mb1, BCH);
        BULK_G2S(sbase + SO_B1, (const void*)gB1[1], BCH, mb1);
    }

    // gather role: 2 threads per edge row
    const int grow  = t >> 1;          // 0..255
    const int ghalf = t & 1;           // which 32-col half
    int gsi = 0, gdi = 0;
    const bool gvalid = (e0 + grow) < E;
    if (gvalid) { gsi = ei[e0 + grow]; gdi = ei[E + e0 + grow]; }
    const uint32_t g_rowoff = (uint32_t)grow * 128;
    const int      g_rx     = grow & 7;

    // stage A chunk c (gather + fp16 convert + swizzled STS)
    auto stageA = [&](int c, uint32_t abo) {
        const float* rp = node + (size_t)(c < 2 ? gdi : gsi) * 128 + (c & 1) * 64 + ghalf * 32;
        #pragma unroll
        for (int u = 0; u < 4; ++u) {
            uint4 H;
            if (gvalid) {
                float4 v0 = *(const float4*)(rp + u * 8);
                float4 v1 = *(const float4*)(rp + u * 8 + 4);
                H.x = packhf2(v0.x, v0.y);
                H.y = packhf2(v0.z, v0.w);
                H.z = packhf2(v1.x, v1.y);
                H.w = packhf2(v1.z, v1.w);
            } else {
                H = make_uint4(0u, 0u, 0u, 0u);
            }
            uint32_t off = g_rowoff + (uint32_t)(((ghalf * 4 + u) ^ g_rx) << 4);
            *(uint4*)(sm + abo + off) = H;
        }
    };

    // ldmatrix per-thread addressing constants
    const int seg = lane >> 3;
    const int lnx = lane & 7;
    const int sA_r = seg & 1;          // A: +8 rows
    const int sA_g = (seg >> 1) & 1;   // A: +16B group
    const int sB_r = (seg >> 1) & 1;   // B: +8 rows
    const int sB_g = seg & 1;          // B: +16B group
    const uint32_t a_rowoff = (uint32_t)(wid * 16 + lnx + sA_r * 8) * 128;
    const uint32_t b_rowoff = (uint32_t)(lnx + sB_r * 8) * 128;

    // MMA over one 64-k chunk (pure fp16)
    auto doChunk = [&](uint32_t Ab, uint32_t Bb, float* cc) {
        #pragma unroll
        for (int ks = 0; ks < 4; ++ks) {
            uint32_t ag = (uint32_t)(((2 * ks) | sA_g) ^ lnx) << 4;
            uint32_t bg = (uint32_t)(((2 * ks) | sB_g) ^ lnx) << 4;
            uint32_t a0,a1,a2,a3;
            LDSM4(a0,a1,a2,a3, sbase + Ab + a_rowoff + ag);
            #pragma unroll
            for (int jb = 0; jb < 8; ++jb) {
                uint32_t baddr = sbase + Bb + b_rowoff + (uint32_t)(jb * 2048) + bg;
                uint32_t b0,b1,b2,b3;
                LDSM4(b0,b1,b2,b3, baddr);
                float* cp0 = cc + 8 * jb;
                float* cp1 = cc + 8 * jb + 4;
                MMA16816(cp0, a0,a1,a2,a3, b0,b1);
                MMA16816(cp1, a0,a1,a2,a3, b2,b3);
            }
        }
    };

    float c1[64];
    #pragma unroll
    for (int i = 0; i < 64; ++i) c1[i] = 0.0f;

    stageA(0, SO_A0);
    __syncthreads();

    uint32_t ph0 = 0, ph1 = 0;

    // ================= GEMM1: 4 k-chunks of 64 ==============================
    #pragma unroll 1
    for (int c = 0; c < 4; ++c) {
        if (c & 1) { mb_wait(mb1, ph1); ph1 ^= 1; }
        else       { mb_wait(mb0, ph0); ph0 ^= 1; }

        if (c < 3) stageA(c + 1, (c & 1) ? SO_A0 : SO_A1);   // writes other A buf

        doChunk((c & 1) ? SO_A1 : SO_A0, (c & 1) ? SO_B1 : SO_B0, c1);
        __syncthreads();

        if (t == 0) {      // refill just-freed B buf with chunk c+2
            const void* nsrc = (c == 0) ? (const void*)gB1[2]
                             : (c == 1) ? (const void*)gB1[3]
                             : (c == 2) ? (const void*)gB2[0]
                                        : (const void*)gB2[1];
            uint32_t dst = (c & 1) ? (sbase + SO_B1) : (sbase + SO_B0);
            uint32_t mb  = (c & 1) ? mb1 : mb0;
            MB_EXPECT(mb, BCH);
            BULK_G2S(dst, nsrc, BCH, mb);
        }
    }

    // ============ epilogue1: relu + rank-1 sqdist + bias -> fp16 to A bufs ===
    const int r0 = wid * 16 + (lane >> 2);
    const int q  = lane & 3;
    const float sq0 = sDS[r0].w;
    const float sq1 = sDS[r0 + 8].w;
    const uint32_t hrow0 = (uint32_t)r0 * 128;
    const int      hrx   = r0 & 7;          // (r0+8)&7 == r0&7
    #pragma unroll
    for (int f = 0; f < 16; ++f) {
        int col = 8 * f + 2 * q;
        float2 b = *(float2*)(sBe1 + col);
        float2 w = *(float2*)(sW256 + col);
        float v0 = fmaxf(c1[4*f+0] + b.x + sq0 * w.x, 0.0f);
        float v1 = fmaxf(c1[4*f+1] + b.y + sq0 * w.y, 0.0f);
        float v2 = fmaxf(c1[4*f+2] + b.x + sq1 * w.x, 0.0f);
        float v3 = fmaxf(c1[4*f+3] + b.y + sq1 * w.y, 0.0f);

        uint32_t h01 = packhf2(v0, v1);
        uint32_t h23 = packhf2(v2, v3);

        uint32_t abuf = (col >> 6) ? SO_A1 : SO_A0;
        int kc = col & 63;
        uint32_t off = hrow0 + (uint32_t)((((kc >> 3) ^ hrx) << 4) | ((kc & 7) << 1));
        *(uint32_t*)(sm + abuf + off)        = h01;
        *(uint32_t*)(sm + abuf + off + 1024) = h23;   // +8 rows = +8*128 B
    }
    __syncwarp();          // A rows are warp-private; warp-level visibility suffices

    // ================= GEMM2: hidden @ We2 ==================================
    float c2[64];
    #pragma unroll
    for (int i = 0; i < 64; ++i) c2[i] = 0.0f;

    mb_wait(mb0, ph0); ph0 ^= 1;
    doChunk(SO_A0, SO_B0, c2);
    mb_wait(mb1, ph1); ph1 ^= 1;
    doChunk(SO_A1, SO_B1, c2);

    // ============ epilogue2: bias, scalar head, register-direct scatter =====
    const int dst0 = sDst[r0];
    const int dst1 = sDst[r0 + 8];
    float w0 = 0.0f, w1 = 0.0f;
    #pragma unroll
    for (int f = 0; f < 16; ++f) {
        int col = 8 * f + 2 * q;
        float2 b  = *(float2*)(sBe2 + col);
        float2 wx = *(float2*)(sWx + col);
        float v0 = c2[4*f+0] + b.x;
        float v1 = c2[4*f+1] + b.y;
        float v2 = c2[4*f+2] + b.x;
        float v3 = c2[4*f+3] + b.y;
        w0 = fmaf(v0, wx.x, fmaf(v1, wx.y, w0));
        w1 = fmaf(v2, wx.x, fmaf(v3, wx.y, w1));
        if (dst0 >= 0) red2(g_mi + (size_t)dst0 * 128 + col, v0, v1);
        if (dst1 >= 0) red2(g_mi + (size_t)dst1 * 128 + col, v2, v3);
    }
    w0 += __shfl_xor_sync(0xffffffffu, w0, 1);
    w0 += __shfl_xor_sync(0xffffffffu, w0, 2);
    w1 += __shfl_xor_sync(0xffffffffu, w1, 1);
    w1 += __shfl_xor_sync(0xffffffffu, w1, 2);
    if (q == 0) {
        sW[r0]     = w0 + bx;
        sW[r0 + 8] = w1 + bx;
    }
    __syncthreads();

    if (t < ET2) {
        int di = sDst[t];
        if (di >= 0) {
            float w = sW[t];
            float4 ds = sDS[t];
            red4(g_dx4 + (size_t)di * 4, make_float4(ds.x * w, ds.y * w, ds.z * w, 0.0f));
        }
    }
}

// ---------------- node kernel (round-1 FFMA, proven) ------------------------
__global__ __launch_bounds__(NTHREADS, 2)
void node_kernel(const float* __restrict__ node,
                 const float* __restrict__ Wh1,
                 const float* __restrict__ bh1,
                 const float* __restrict__ Wh2,
                 const float* __restrict__ bh2,
                 float* __restrict__ outH,
                 int N)
{
    extern __shared__ float s[];
    float* sAH = s;
    float* sB  = s + 256 * SA;

    const int t  = threadIdx.x;
    const int r0 = blockIdx.x * TILE;

    {
        int n   = t & 63;
        int c   = t >> 6;
        int row = r0 + n;
        if (row < N) {
            const float* srow = (c < 2) ? (node + (size_t)row * Fdim + c * 64)
                                        : (g_mi + (size_t)row * 128 + (c - 2) * 64);
            int kb = c * 64;
            #pragma unroll
            for (int r = 0; r < 16; ++r) {
                float4 v = *(const float4*)(srow + r * 4);
                int k = kb + r * 4;
                sAH[(k + 0) * SA + n] = v.x;
                sAH[(k + 1) * SA + n] = v.y;
                sAH[(k + 2) * SA + n] = v.z;
                sAH[(k + 3) * SA + n] = v.w;
            }
        }
    }
    __syncthreads();

    const int m = t & 15;
    const int g = t >> 4;

    float acc[4][8];
    {
        float4 b0 = *(const float4*)(bh1 + g * 8);
        float4 b1 = *(const float4*)(bh1 + g * 8 + 4);
        #pragma unroll
        for (int i = 0; i < 4; ++i) {
            acc[i][0] = b0.x; acc[i][1] = b0.y; acc[i][2] = b0.z; acc[i][3] = b0.w;
            acc[i][4] = b1.x; acc[i][5] = b1.y; acc[i][6] = b1.z; acc[i][7] = b1.w;
        }
    }

    for (int kk = 0; kk < 256; kk += 16) {
        {
            int idx = t * 8;
            int r   = idx >> 7;
            int cc  = idx & 127;
            const float* src = Wh1 + (size_t)(kk + r) * 128 + cc;
            *(float4*)(sB + idx)     = *(const float4*)src;
            *(float4*)(sB + idx + 4) = *(const float4*)(src + 4);
        }
        __syncthreads();
        #pragma unroll
        for (int k = 0; k < 16; ++k) {
            float4 a  = *(const float4*)(sAH + (kk + k) * SA + m * 4);
            float4 w0 = *(const float4*)(sB + k * 128 + g * 8);
            float4 w1 = *(const float4*)(sB + k * 128 + g * 8 + 4);
            float av[4] = {a.x, a.y, a.z, a.w};
            float wv[8] = {w0.x, w0.y, w0.z, w0.w, w1.x, w1.y, w1.z, w1.w};
            #pragma unroll
            for (int i = 0; i < 4; ++i)
                #pragma unroll
                for (int j = 0; j < 8; ++j)
                    acc[i][j] = fmaf(av[i], wv[j], acc[i][j]);
        }
        __syncthreads();
    }

    #pragma unroll
    for (int j = 0; j < 8; ++j) {
        int h = g * 8 + j;
        float4 v;
        v.x = fmaxf(acc[0][j], 0.0f);
        v.y = fmaxf(acc[1][j], 0.0f);
        v.z = fmaxf(acc[2][j], 0.0f);
        v.w = fmaxf(acc[3][j], 0.0f);
        *(float4*)(sAH + h * SA + m * 4) = v;
    }
    __syncthreads();

    float acc2[4][8];
    {
        float4 b0 = *(const float4*)(bh2 + g * 8);
        float4 b1 = *(const float4*)(bh2 + g * 8 + 4);
        #pragma unroll
        for (int i = 0; i < 4; ++i) {
            acc2[i][0] = b0.x; acc2[i][1] = b0.y; acc2[i][2] = b0.z; acc2[i][3] = b0.w;
            acc2[i][4] = b1.x; acc2[i][5] = b1.y; acc2[i][6] = b1.z; acc2[i][7] = b1.w;
        }
    }

    for (int kk = 0; kk < 128; kk += 16) {
        {
            int idx = t * 8;
            int r   = idx >> 7;
            int cc  = idx & 127;
            const float* src = Wh2 + (size_t)(kk + r) * Fdim + cc;
            *(float4*)(sB + idx)     = *(const float4*)src;
            *(float4*)(sB + idx + 4) = *(const float4*)(src + 4);
        }
        __syncthreads();
        #pragma unroll
        for (int k = 0; k < 16; ++k) {
            float4 a  = *(const float4*)(sAH + (kk + k) * SA + m * 4);
            float4 w0 = *(const float4*)(sB + k * 128 + g * 8);
            float4 w1 = *(const float4*)(sB + k * 128 + g * 8 + 4);
            float av[4] = {a.x, a.y, a.z, a.w};
            float wv[8] = {w0.x, w0.y, w0.z, w0.w, w1.x, w1.y, w1.z, w1.w};
            #pragma unroll
            for (int i = 0; i < 4; ++i)
                #pragma unroll
                for (int j = 0; j < 8; ++j)
                    acc2[i][j] = fmaf(av[i], wv[j], acc2[i][j]);
        }
        __syncthreads();
    }

    #pragma unroll
    for (int i = 0; i < 4; ++i) {
        int row = r0 + m * 4 + i;
        if (row < N) {
            float4 v0, v1;
            v0.x = acc2[i][0]; v0.y = acc2[i][1]; v0.z = acc2[i][2]; v0.w = acc2[i][3];
            v1.x = acc2[i][4]; v1.y = acc2[i][5]; v1.z = acc2[i][6]; v1.w = acc2[i][7];
            *(float4*)(outH + (size_t)row * Fdim + g * 8)     = v0;
            *(float4*)(outH + (size_t)row * Fdim + g * 8 + 4) = v1;
        }
    }
}

// ---------------- coordinate update -----------------------------------------
__global__ void x_kernel(const float* __restrict__ coord,
                         float* __restrict__ outX,
                         int n3, float C)
{
    int i = blockIdx.x * blockDim.x + threadIdx.x;
    if (i < n3) {
        int n = i / 3, d = i - n * 3;
        outX[i] = coord[i] + g_dx4[(size_t)n * 4 + d] * C;
    }
}

// ---------------- launch -----------------------------------------------------
extern "C" void kernel_launch(void* const* d_in, const int* in_sizes, int n_in,
                              void* d_out, int out_size)
{
    const float* node  = (const float*)d_in[0];
    const float* coord = (const float*)d_in[1];
    const int*   ei    = (const int*)d_in[2];
    const float* We1   = (const float*)d_in[3];
    const float* be1   = (const float*)d_in[4];
    const float* We2   = (const float*)d_in[5];
    const float* be2   = (const float*)d_in[6];
    const float* Wx    = (const float*)d_in[7];
    const float* bx    = (const float*)d_in[8];
    const float* Wh1   = (const float*)d_in[9];
    const float* bh1   = (const float*)d_in[10];
    const float* Wh2   = (const float*)d_in[11];
    const float* bh2   = (const float*)d_in[12];

    const int N = in_sizes[0] / Fdim;
    const int E = in_sizes[2] / 2;

    float* outH = (float*)d_out;
    float* outX = outH + (size_t)N * Fdim;

    const int node_smem = (256 * SA + 16 * 128) * 4;
    cudaFuncSetAttribute(edge_kernel, cudaFuncAttributeMaxDynamicSharedMemorySize, EDGE_SMEM);
    cudaFuncSetAttribute(node_kernel, cudaFuncAttributeMaxDynamicSharedMemorySize, node_smem);

    prep_kernel<<<(49152 + 255) / 256, 256>>>(We1, We2);
    {
        int n_mi = N * 128;
        zero_kernel<<<(n_mi + 255) / 256, 256>>>(n_mi, N * 4);
    }
    {
        int grid = (E + ET2 - 1) / ET2;
        edge_kernel<<<grid, 512, EDGE_SMEM>>>(node, coord, ei, We1, be1, be2, Wx, bx, E);
    }
    {
        int grid = (N + TILE - 1) / TILE;
        node_kernel<<<grid, NTHREADS, node_smem>>>(node, Wh1, bh1, Wh2, bh2, outH, N);
    }
    {
        int n3 = N * 3;
        float C = 1.0f / (float)(N - 1);
        x_kernel<<<(n3 + 255) / 256, 256>>>(coord, outX, n3, C);
    }
}

// round 8
// speedup vs baseline: 5.3653x; 1.6104x over previous
#include <cuda_runtime.h>
#include <cuda_fp16.h>
#include <cstdint>

#define Fdim 128
#define ET2  256              // rows per CTA tile (MMA M)
#define MAXN 50000

// ---------------- scratch (static device arrays; allocation-free) ----------
__device__ float g_mi[(size_t)MAXN * 128];
__device__ float g_dx4[(size_t)MAXN * 4];
__device__ __align__(16) __half g_nodeh[(size_t)MAXN * 128];   // fp16 node table
// swizzled fp16 weight chunk images: rows=n(128), kc(64)
__device__ __align__(16) __half gB1[4][8192];   // We1
__device__ __align__(16) __half gB2[2][8192];   // We2
__device__ __align__(16) __half gH1[4][8192];   // Wh1
__device__ __align__(16) __half gH2[2][8192];   // Wh2

#define BCH 16384            /* bytes per B chunk */

// ---------------- PTX helpers ----------------------------------------------
__device__ __forceinline__ uint32_t smem_u32(const void* p) {
    uint32_t a;
    asm("{ .reg .u64 t; cvta.to.shared.u64 t, %1; cvt.u32.u64 %0, t; }" : "=r"(a) : "l"(p));
    return a;
}

#define LDSM4(r0, r1, r2, r3, addr) \
    asm volatile("ldmatrix.sync.aligned.m8n8.x4.shared.b16 {%0,%1,%2,%3}, [%4];" \
                 : "=r"(r0), "=r"(r1), "=r"(r2), "=r"(r3) : "r"(addr))

#define MMA16816(cp, a0, a1, a2, a3, b0, b1) \
    asm volatile("mma.sync.aligned.m16n8k16.row.col.f32.f16.f16.f32 " \
                 "{%0,%1,%2,%3},{%4,%5,%6,%7},{%8,%9},{%0,%1,%2,%3};" \
                 : "+f"((cp)[0]), "+f"((cp)[1]), "+f"((cp)[2]), "+f"((cp)[3]) \
                 : "r"(a0), "r"(a1), "r"(a2), "r"(a3), "r"(b0), "r"(b1))

#define MB_INIT(mb, c) asm volatile("mbarrier.init.shared.b64 [%0], %1;" :: "r"(mb), "r"(c) : "memory")
#define MB_EXPECT(mb, b) asm volatile("mbarrier.arrive.expect_tx.shared.b64 _, [%0], %1;" :: "r"(mb), "r"(b) : "memory")
#define BULK_G2S(dst, src, bytes, mb) \
    asm volatile("cp.async.bulk.shared::cluster.global.mbarrier::complete_tx::bytes [%0], [%1], %2, [%3];" \
                 :: "r"(dst), "l"(src), "r"(bytes), "r"(mb) : "memory")

#define CPA16(dst, src, n) \
    asm volatile("cp.async.cg.shared.global [%0], [%1], 16, %2;" :: "r"(dst), "l"(src), "r"(n) : "memory")
#define CPA_COMMIT() asm volatile("cp.async.commit_group;" ::: "memory")
#define CPA_WAIT0()  asm volatile("cp.async.wait_group 0;" ::: "memory")

__device__ __forceinline__ void mb_wait(uint32_t mb, uint32_t parity) {
    uint32_t done;
    asm volatile("{ .reg .pred p; mbarrier.try_wait.parity.acquire.cta.shared::cta.b64 p, [%1], %2; selp.b32 %0, 1, 0, p; }"
                 : "=r"(done) : "r"(mb), "r"(parity) : "memory");
    if (!done) {
        asm volatile("{ .reg .pred P1;\nW%=:\n mbarrier.try_wait.parity.acquire.cta.shared::cta.b64 P1, [%0], %1, 0x989680;\n @P1 bra.uni D%=;\n bra.uni W%=;\nD%=:\n}"
                     :: "r"(mb), "r"(parity) : "memory");
    }
}

__device__ __forceinline__ void red2(float* p, float x, float y) {
    asm volatile("red.global.add.v2.f32 [%0], {%1,%2};" :: "l"(p), "f"(x), "f"(y) : "memory");
}
__device__ __forceinline__ void red4(float* p, float4 v) {
    asm volatile("red.global.add.v4.f32 [%0], {%1,%2,%3,%4};"
                 :: "l"(p), "f"(v.x), "f"(v.y), "f"(v.z), "f"(v.w) : "memory");
}

__device__ __forceinline__ uint32_t packhf2(float a, float b) {
    uint32_t r;
    asm("cvt.rn.f16x2.f32 %0, %1, %2;" : "=r"(r) : "f"(b), "f"(a));
    return r;
}

// swizzled element offset within a [row][kc] tile, 64 fp16 per row (128 B)
__host__ __device__ __forceinline__ int swoff(int n, int kc) {
    return n * 64 + ((((kc >> 3) ^ (n & 7)) << 3) | (kc & 7));
}

// ---------------- prep: swizzled fp16 weight chunk images -------------------
__global__ void prep_kernel(const float* __restrict__ We1, const float* __restrict__ We2,
                            const float* __restrict__ Wh1, const float* __restrict__ Wh2)
{
    int id = blockIdx.x * blockDim.x + threadIdx.x;
    if (id < 32768) {
        int c = id >> 13, rem = id & 8191, n = rem >> 6, kc = rem & 63;
        gB1[c][swoff(n, kc)] = __float2half_rn(We1[(size_t)(c * 64 + kc) * 128 + n]);
    } else if (id < 49152) {
        int id2 = id - 32768;
        int c = id2 >> 13, rem = id2 & 8191, n = rem >> 6, kc = rem & 63;
        gB2[c][swoff(n, kc)] = __float2half_rn(We2[(size_t)(c * 64 + kc) * 128 + n]);
    } else if (id < 81920) {
        int id2 = id - 49152;
        int c = id2 >> 13, rem = id2 & 8191, n = rem >> 6, kc = rem & 63;
        gH1[c][swoff(n, kc)] = __float2half_rn(Wh1[(size_t)(c * 64 + kc) * 128 + n]);
    } else if (id < 98304) {
        int id2 = id - 81920;
        int c = id2 >> 13, rem = id2 & 8191, n = rem >> 6, kc = rem & 63;
        gH2[c][swoff(n, kc)] = __float2half_rn(Wh2[(size_t)(c * 64 + kc) * 128 + n]);
    }
}

// ---------------- zero scratch + convert node table to fp16 -----------------
__global__ void zero_kernel(const float* __restrict__ node, int n_mi, int n_dx)
{
    int i = blockIdx.x * blockDim.x + threadIdx.x;
    if (i < n_mi) {
        g_mi[i] = 0.0f;
        g_nodeh[i] = __float2half_rn(node[i]);
    }
    if (i < n_dx) g_dx4[i] = 0.0f;
}

// ---------------- edge kernel ------------------------------------------------
// SMEM layout (bytes): A buffers 256 rows x 64 kc fp16 (32K each); B bufs 16K
#define SO_A0   0
#define SO_A1   32768
#define SO_B0   65536
#define SO_B1   81920
#define SO_DS   98304      /* float4[256] */
#define SO_W    102400     /* float[256] */
#define SO_DST  103424     /* int[256] */
#define SO_WX   104448
#define SO_BE1  104960
#define SO_BE2  105472
#define SO_W256 105984
#define SO_MB   106496
#define EDGE_SMEM 106528

__global__ __launch_bounds__(512, 1)
void edge_kernel(const float* __restrict__ coord,
                 const int*   __restrict__ ei,
                 const float* __restrict__ We1,
                 const float* __restrict__ be1,
                 const float* __restrict__ be2,
                 const float* __restrict__ Wx,
                 const float* __restrict__ bxp,
                 int E)
{
    extern __shared__ char sm[];
    const uint32_t sbase = smem_u32(sm);

    float4* sDS  = (float4*)(sm + SO_DS);
    float*  sW   = (float*)(sm + SO_W);
    int*    sDst = (int*)(sm + SO_DST);
    float*  sWx  = (float*)(sm + SO_WX);
    float*  sBe1 = (float*)(sm + SO_BE1);
    float*  sBe2 = (float*)(sm + SO_BE2);
    float*  sW256= (float*)(sm + SO_W256);

    const int t    = threadIdx.x;
    const int wid  = t >> 5;
    const int lane = t & 31;
    const int e0   = blockIdx.x * ET2;
    const float bx = bxp[0];

    const uint32_t mb0 = sbase + SO_MB;
    const uint32_t mb1 = sbase + SO_MB + 8;

    if (t == 0) { MB_INIT(mb0, 1); MB_INIT(mb1, 1); }

    // ---- per-edge metadata ----
    if (t < ET2) {
        int eg = e0 + t;
        float dx = 0.f, dy = 0.f, dz = 0.f;
        int di = -1;
        if (eg < E) {
            int si = ei[eg];
            di     = ei[E + eg];
            dx = coord[(size_t)di * 3 + 0] - coord[(size_t)si * 3 + 0];
            dy = coord[(size_t)di * 3 + 1] - coord[(size_t)si * 3 + 1];
            dz = coord[(size_t)di * 3 + 2] - coord[(size_t)si * 3 + 2];
        }
        sDS[t]  = make_float4(dx, dy, dz, dx * dx + dy * dy + dz * dz);
        sDst[t] = di;
    }
    if (t < 128) {
        sWx[t]  = Wx[t];
        sBe1[t] = be1[t];
        sBe2[t] = be2[t];
        sW256[t]= We1[(size_t)256 * 128 + t];
    }
    __syncthreads();

    // launch first two B chunk copies
    if (t == 0) {
        MB_EXPECT(mb0, BCH);
        BULK_G2S(sbase + SO_B0, (const void*)gB1[0], BCH, mb0);
        MB_EXPECT(mb1, BCH);
        BULK_G2S(sbase + SO_B1, (const void*)gB1[1], BCH, mb1);
    }

    // gather role: 2 threads per edge row
    const int grow  = t >> 1;          // 0..255
    const int ghalf = t & 1;           // which 32-col half
    int gsi = 0, gdi = 0;
    const bool gvalid = (e0 + grow) < E;
    if (gvalid) { gsi = ei[e0 + grow]; gdi = ei[E + e0 + grow]; }
    const uint32_t g_rowoff = (uint32_t)grow * 128;
    const int      g_rx     = grow & 7;
    const uint32_t g_nsz    = gvalid ? 16u : 0u;

    // stage A chunk c via cp.async from fp16 node table (zfill when invalid)
    auto stageA = [&](int c, uint32_t abo) {
        const __half* rp = g_nodeh + (size_t)(c < 2 ? gdi : gsi) * 128 + (c & 1) * 64 + ghalf * 32;
        #pragma unroll
        for (int u = 0; u < 4; ++u) {
            uint32_t dst = sbase + abo + g_rowoff + (uint32_t)(((ghalf * 4 + u) ^ g_rx) << 4);
            CPA16(dst, rp + u * 8, g_nsz);
        }
        CPA_COMMIT();
    };

    // ldmatrix per-thread addressing constants
    const int seg = lane >> 3;
    const int lnx = lane & 7;
    const int sA_r = seg & 1;
    const int sA_g = (seg >> 1) & 1;
    const int sB_r = (seg >> 1) & 1;
    const int sB_g = seg & 1;
    const uint32_t a_rowoff = (uint32_t)(wid * 16 + lnx + sA_r * 8) * 128;
    const uint32_t b_rowoff = (uint32_t)(lnx + sB_r * 8) * 128;

    auto doChunk = [&](uint32_t Ab, uint32_t Bb, float* cc) {
        #pragma unroll
        for (int ks = 0; ks < 4; ++ks) {
            uint32_t ag = (uint32_t)(((2 * ks) | sA_g) ^ lnx) << 4;
            uint32_t bg = (uint32_t)(((2 * ks) | sB_g) ^ lnx) << 4;
            uint32_t a0,a1,a2,a3;
            LDSM4(a0,a1,a2,a3, sbase + Ab + a_rowoff + ag);
            #pragma unroll
            for (int jb = 0; jb < 8; ++jb) {
                uint32_t baddr = sbase + Bb + b_rowoff + (uint32_t)(jb * 2048) + bg;
                uint32_t b0,b1,b2,b3;
                LDSM4(b0,b1,b2,b3, baddr);
                float* cp0 = cc + 8 * jb;
                float* cp1 = cc + 8 * jb + 4;
                MMA16816(cp0, a0,a1,a2,a3, b0,b1);
                MMA16816(cp1, a0,a1,a2,a3, b2,b3);
            }
        }
    };

    float c1[64];
    #pragma unroll
    for (int i = 0; i < 64; ++i) c1[i] = 0.0f;

    stageA(0, SO_A0);
    CPA_WAIT0();
    __syncthreads();

    uint32_t ph0 = 0, ph1 = 0;

    // ================= GEMM1: 4 k-chunks of 64 ==============================
    #pragma unroll 1
    for (int c = 0; c < 4; ++c) {
        if (c & 1) { mb_wait(mb1, ph1); ph1 ^= 1; }
        else       { mb_wait(mb0, ph0); ph0 ^= 1; }

        if (c < 3) stageA(c + 1, (c & 1) ? SO_A0 : SO_A1);

        doChunk((c & 1) ? SO_A1 : SO_A0, (c & 1) ? SO_B1 : SO_B0, c1);
        CPA_WAIT0();
        __syncthreads();

        if (t == 0) {
            const void* nsrc = (c == 0) ? (const void*)gB1[2]
                             : (c == 1) ? (const void*)gB1[3]
                             : (c == 2) ? (const void*)gB2[0]
                                        : (const void*)gB2[1];
            uint32_t dst = (c & 1) ? (sbase + SO_B1) : (sbase + SO_B0);
            uint32_t mb  = (c & 1) ? mb1 : mb0;
            MB_EXPECT(mb, BCH);
            BULK_G2S(dst, nsrc, BCH, mb);
        }
    }

    // ============ epilogue1: relu + rank-1 sqdist + bias -> fp16 to A bufs ===
    const int r0 = wid * 16 + (lane >> 2);
    const int q  = lane & 3;
    const float sq0 = sDS[r0].w;
    const float sq1 = sDS[r0 + 8].w;
    const uint32_t hrow0 = (uint32_t)r0 * 128;
    const int      hrx   = r0 & 7;
    #pragma unroll
    for (int f = 0; f < 16; ++f) {
        int col = 8 * f + 2 * q;
        float2 b = *(float2*)(sBe1 + col);
        float2 w = *(float2*)(sW256 + col);
        float v0 = fmaxf(c1[4*f+0] + b.x + sq0 * w.x, 0.0f);
        float v1 = fmaxf(c1[4*f+1] + b.y + sq0 * w.y, 0.0f);
        float v2 = fmaxf(c1[4*f+2] + b.x + sq1 * w.x, 0.0f);
        float v3 = fmaxf(c1[4*f+3] + b.y + sq1 * w.y, 0.0f);

        uint32_t h01 = packhf2(v0, v1);
        uint32_t h23 = packhf2(v2, v3);

        uint32_t abuf = (col >> 6) ? SO_A1 : SO_A0;
        int kc = col & 63;
        uint32_t off = hrow0 + (uint32_t)((((kc >> 3) ^ hrx) << 4) | ((kc & 7) << 1));
        *(uint32_t*)(sm + abuf + off)        = h01;
        *(uint32_t*)(sm + abuf + off + 1024) = h23;
    }
    __syncwarp();

    // ================= GEMM2: hidden @ We2 ==================================
    float c2[64];
    #pragma unroll
    for (int i = 0; i < 64; ++i) c2[i] = 0.0f;

    mb_wait(mb0, ph0); ph0 ^= 1;
    doChunk(SO_A0, SO_B0, c2);
    mb_wait(mb1, ph1); ph1 ^= 1;
    doChunk(SO_A1, SO_B1, c2);

    // ============ epilogue2: bias, scalar head, register-direct scatter =====
    const int dst0 = sDst[r0];
    const int dst1 = sDst[r0 + 8];
    float w0 = 0.0f, w1 = 0.0f;
    #pragma unroll
    for (int f = 0; f < 16; ++f) {
        int col = 8 * f + 2 * q;
        float2 b  = *(float2*)(sBe2 + col);
        float2 wx = *(float2*)(sWx + col);
        float v0 = c2[4*f+0] + b.x;
        float v1 = c2[4*f+1] + b.y;
        float v2 = c2[4*f+2] + b.x;
        float v3 = c2[4*f+3] + b.y;
        w0 = fmaf(v0, wx.x, fmaf(v1, wx.y, w0));
        w1 = fmaf(v2, wx.x, fmaf(v3, wx.y, w1));
        if (dst0 >= 0) red2(g_mi + (size_t)dst0 * 128 + col, v0, v1);
        if (dst1 >= 0) red2(g_mi + (size_t)dst1 * 128 + col, v2, v3);
    }
    w0 += __shfl_xor_sync(0xffffffffu, w0, 1);
    w0 += __shfl_xor_sync(0xffffffffu, w0, 2);
    w1 += __shfl_xor_sync(0xffffffffu, w1, 1);
    w1 += __shfl_xor_sync(0xffffffffu, w1, 2);
    if (q == 0) {
        sW[r0]     = w0 + bx;
        sW[r0 + 8] = w1 + bx;
    }
    __syncthreads();

    if (t < ET2) {
        int di = sDst[t];
        if (di >= 0) {
            float w = sW[t];
            float4 ds = sDS[t];
            red4(g_dx4 + (size_t)di * 4, make_float4(ds.x * w, ds.y * w, ds.z * w, 0.0f));
        }
    }
}

// ---------------- node kernel: fp16 MMA [node|m_i] @ Wh1 -> relu -> @ Wh2 ---
#define NO_BH1 98304
#define NO_BH2 98816
#define NO_MB  99328
#define NODE_SMEM 99360

__global__ __launch_bounds__(512, 1)
void node_kernel(const float* __restrict__ bh1,
                 const float* __restrict__ bh2,
                 float* __restrict__ outH,
                 int N)
{
    extern __shared__ char sm[];
    const uint32_t sbase = smem_u32(sm);

    float* sBh1 = (float*)(sm + NO_BH1);
    float* sBh2 = (float*)(sm + NO_BH2);

    const int t    = threadIdx.x;
    const int wid  = t >> 5;
    const int lane = t & 31;
    const int n0   = blockIdx.x * ET2;

    const uint32_t mb0 = sbase + NO_MB;
    const uint32_t mb1 = sbase + NO_MB + 8;

    if (t == 0) { MB_INIT(mb0, 1); MB_INIT(mb1, 1); }
    if (t < 128) {
        sBh1[t] = bh1[t];
        sBh2[t] = bh2[t];
    }
    __syncthreads();

    if (t == 0) {
        MB_EXPECT(mb0, BCH);
        BULK_G2S(sbase + SO_B0, (const void*)gH1[0], BCH, mb0);
        MB_EXPECT(mb1, BCH);
        BULK_G2S(sbase + SO_B1, (const void*)gH1[1], BCH, mb1);
    }

    const int grow  = t >> 1;
    const int ghalf = t & 1;
    const int grnode = n0 + grow;
    const bool gvalid = grnode < N;
    const int grclamp = gvalid ? grnode : 0;
    const uint32_t g_rowoff = (uint32_t)grow * 128;
    const int      g_rx     = grow & 7;
    const uint32_t g_nsz    = gvalid ? 16u : 0u;

    // chunks 0,1: fp16 node table via cp.async
    auto stageN = [&](int c, uint32_t abo) {
        const __half* rp = g_nodeh + (size_t)grclamp * 128 + c * 64 + ghalf * 32;
        #pragma unroll
        for (int u = 0; u < 4; ++u) {
            uint32_t dst = sbase + abo + g_rowoff + (uint32_t)(((ghalf * 4 + u) ^ g_rx) << 4);
            CPA16(dst, rp + u * 8, g_nsz);
        }
        CPA_COMMIT();
    };
    // chunks 2,3: fp32 m_i -> fp16 convert + swizzled STS
    auto stageM = [&](int c, uint32_t abo) {
        const float* rp = g_mi + (size_t)grclamp * 128 + (c - 2) * 64 + ghalf * 32;
        #pragma unroll
        for (int u = 0; u < 4; ++u) {
            uint4 H;
            if (gvalid) {
                float4 v0 = *(const float4*)(rp + u * 8);
                float4 v1 = *(const float4*)(rp + u * 8 + 4);
                H.x = packhf2(v0.x, v0.y);
                H.y = packhf2(v0.z, v0.w);
                H.z = packhf2(v1.x, v1.y);
                H.w = packhf2(v1.z, v1.w);
            } else {
                H = make_uint4(0u, 0u, 0u, 0u);
            }
            uint32_t off = g_rowoff + (uint32_t)(((ghalf * 4 + u) ^ g_rx) << 4);
            *(uint4*)(sm + abo + off) = H;
        }
    };

    const int seg = lane >> 3;
    const int lnx = lane & 7;
    const int sA_r = seg & 1;
    const int sA_g = (seg >> 1) & 1;
    const int sB_r = (seg >> 1) & 1;
    const int sB_g = seg & 1;
    const uint32_t a_rowoff = (uint32_t)(wid * 16 + lnx + sA_r * 8) * 128;
    const uint32_t b_rowoff = (uint32_t)(lnx + sB_r * 8) * 128;

    auto doChunk = [&](uint32_t Ab, uint32_t Bb, float* cc) {
        #pragma unroll
        for (int ks = 0; ks < 4; ++ks) {
            uint32_t ag = (uint32_t)(((2 * ks) | sA_g) ^ lnx) << 4;
            uint32_t bg = (uint32_t)(((2 * ks) | sB_g) ^ lnx) << 4;
            uint32_t a0,a1,a2,a3;
            LDSM4(a0,a1,a2,a3, sbase + Ab + a_rowoff + ag);
            #pragma unroll
            for (int jb = 0; jb < 8; ++jb) {
                uint32_t baddr = sbase + Bb + b_rowoff + (uint32_t)(jb * 2048) + bg;
                uint32_t b0,b1,b2,b3;
                LDSM4(b0,b1,b2,b3, baddr);
                float* cp0 = cc + 8 * jb;
                float* cp1 = cc + 8 * jb + 4;
                MMA16816(cp0, a0,a1,a2,a3, b0,b1);
                MMA16816(cp1, a0,a1,a2,a3, b2,b3);
            }
        }
    };

    float c1[64];
    #pragma unroll
    for (int i = 0; i < 64; ++i) c1[i] = 0.0f;

    stageN(0, SO_A0);
    CPA_WAIT0();
    __syncthreads();

    uint32_t ph0 = 0, ph1 = 0;

    #pragma unroll 1
    for (int c = 0; c < 4; ++c) {
        if (c & 1) { mb_wait(mb1, ph1); ph1 ^= 1; }
        else       { mb_wait(mb0, ph0); ph0 ^= 1; }

        if (c == 0)      stageN(1, SO_A1);
        else if (c == 1) stageM(2, SO_A0);
        else if (c == 2) stageM(3, SO_A1);

        doChunk((c & 1) ? SO_A1 : SO_A0, (c & 1) ? SO_B1 : SO_B0, c1);
        CPA_WAIT0();
        __syncthreads();

        if (t == 0) {
            const void* nsrc = (c == 0) ? (const void*)gH1[2]
                             : (c == 1) ? (const void*)gH1[3]
                             : (c == 2) ? (const void*)gH2[0]
                                        : (const void*)gH2[1];
            uint32_t dst = (c & 1) ? (sbase + SO_B1) : (sbase + SO_B0);
            uint32_t mb  = (c & 1) ? mb1 : mb0;
            MB_EXPECT(mb, BCH);
            BULK_G2S(dst, nsrc, BCH, mb);
        }
    }

    // epilogue1: relu + bias -> fp16 hidden into A bufs
    const int r0 = wid * 16 + (lane >> 2);
    const int q  = lane & 3;
    const uint32_t hrow0 = (uint32_t)r0 * 128;
    const int      hrx   = r0 & 7;
    #pragma unroll
    for (int f = 0; f < 16; ++f) {
        int col = 8 * f + 2 * q;
        float2 b = *(float2*)(sBh1 + col);
        float v0 = fmaxf(c1[4*f+0] + b.x, 0.0f);
        float v1 = fmaxf(c1[4*f+1] + b.y, 0.0f);
        float v2 = fmaxf(c1[4*f+2] + b.x, 0.0f);
        float v3 = fmaxf(c1[4*f+3] + b.y, 0.0f);

        uint32_t h01 = packhf2(v0, v1);
        uint32_t h23 = packhf2(v2, v3);

        uint32_t abuf = (col >> 6) ? SO_A1 : SO_A0;
        int kc = col & 63;
        uint32_t off = hrow0 + (uint32_t)((((kc >> 3) ^ hrx) << 4) | ((kc & 7) << 1));
        *(uint32_t*)(sm + abuf + off)        = h01;
        *(uint32_t*)(sm + abuf + off + 1024) = h23;
    }
    __syncwarp();

    float c2[64];
    #pragma unroll
    for (int i = 0; i < 64; ++i) c2[i] = 0.0f;

    mb_wait(mb0, ph0); ph0 ^= 1;
    doChunk(SO_A0, SO_B0, c2);
    mb_wait(mb1, ph1); ph1 ^= 1;
    doChunk(SO_A1, SO_B1, c2);

    // epilogue2: bias + store h_new
    const int row0 = n0 + r0;
    const int row1 = row0 + 8;
    #pragma unroll
    for (int f = 0; f < 16; ++f) {
        int col = 8 * f + 2 * q;
        float2 b = *(float2*)(sBh2 + col);
        if (row0 < N) {
            float2 v; v.x = c2[4*f+0] + b.x; v.y = c2[4*f+1] + b.y;
            *(float2*)(outH + (size_t)row0 * Fdim + col) = v;
        }
        if (row1 < N) {
            float2 v; v.x = c2[4*f+2] + b.x; v.y = c2[4*f+3] + b.y;
            *(float2*)(outH + (size_t)row1 * Fdim + col) = v;
        }
    }
}

// ---------------- coordinate update -----------------------------------------
__global__ void x_kernel(const float* __restrict__ coord,
                         float* __restrict__ outX,
                         int n3, float C)
{
    int i = blockIdx.x * blockDim.x + threadIdx.x;
    if (i < n3) {
        int n = i / 3, d = i - n * 3;
        outX[i] = coord[i] + g_dx4[(size_t)n * 4 + d] * C;
    }
}

// ---------------- launch -----------------------------------------------------
extern "C" void kernel_launch(void* const* d_in, const int* in_sizes, int n_in,
                              void* d_out, int out_size)
{
    const float* node  = (const float*)d_in[0];
    const float* coord = (const float*)d_in[1];
    const int*   ei    = (const int*)d_in[2];
    const float* We1   = (const float*)d_in[3];
    const float* be1   = (const float*)d_in[4];
    const float* We2   = (const float*)d_in[5];
    const float* be2   = (const float*)d_in[6];
    const float* Wx    = (const float*)d_in[7];
    const float* bx    = (const float*)d_in[8];
    const float* Wh1   = (const float*)d_in[9];
    const float* bh1   = (const float*)d_in[10];
    const float* Wh2   = (const float*)d_in[11];
    const float* bh2   = (const float*)d_in[12];

    const int N = in_sizes[0] / Fdim;
    const int E = in_sizes[2] / 2;

    float* outH = (float*)d_out;
    float* outX = outH + (size_t)N * Fdim;

    cudaFuncSetAttribute(edge_kernel, cudaFuncAttributeMaxDynamicSharedMemorySize, EDGE_SMEM);
    cudaFuncSetAttribute(node_kernel, cudaFuncAttributeMaxDynamicSharedMemorySize, NODE_SMEM);

    prep_kernel<<<(98304 + 255) / 256, 256>>>(We1, We2, Wh1, Wh2);
    {
        int n_mi = N * 128;
        zero_kernel<<<(n_mi + 255) / 256, 256>>>(node, n_mi, N * 4);
    }
    {
        int grid = (E + ET2 - 1) / ET2;
        edge_kernel<<<grid, 512, EDGE_SMEM>>>(coord, ei, We1, be1, be2, Wx, bx, E);
    }
    {
        int grid = (N + ET2 - 1) / ET2;
        node_kernel<<<grid, 512, NODE_SMEM>>>(bh1, bh2, outH, N);
    }
    {
        int n3 = N * 3;
        float C = 1.0f / (float)(N - 1);
        x_kernel<<<(n3 + 255) / 256, 256>>>(coord, outX, n3, C);
    }
}